// round 12
// baseline (speedup 1.0000x reference)
#include <cuda_runtime.h>
#include <cuda_bf16.h>
#include <math.h>

// ---------------- problem constants ----------------
#define N_TOK 16384
#define KCB   16384
#define DDIM  256
#define NBATCH 16
#define HWD   1024

#define O_OUT   0
#define O_SCAL  4194304
#define O_WNEW  4194308
#define O_CNEW  8388612
#define O_EANEW 8404996

#define CAPQ   16
#define NSUB   16
#define MARGIN 1e-3f

// ---------------- device scratch ----------------
__device__ float g_zf[N_TOK * DDIM];
__device__ float g_wsq[KCB];
__device__ float g_zsq[N_TOK];
__device__ int   g_token[N_TOK];
__device__ float g_counts[KCB];
__device__ float g_esum[KCB * DDIM];
__device__ float g_scal[8];
__device__ __nv_bfloat16 g_zbf[N_TOK * DDIM];
__device__ __nv_bfloat16 g_wbf[KCB * DDIM];
__device__ int g_cand[N_TOK * NSUB * CAPQ];
__device__ int g_ccnt[N_TOK * NSUB];

// ---------------- helpers ----------------
__device__ __forceinline__ void cp_async16(void* smem_dst, const void* gsrc) {
    unsigned sa = (unsigned)__cvta_generic_to_shared(smem_dst);
    asm volatile("cp.async.cg.shared.global [%0], [%1], 16;" :: "r"(sa), "l"(gsrc));
}
#define CP_COMMIT() asm volatile("cp.async.commit_group;")

__device__ __forceinline__ void ldsm_x4(unsigned addr, unsigned& r0, unsigned& r1,
                                        unsigned& r2, unsigned& r3) {
    asm volatile("ldmatrix.sync.aligned.m8n8.x4.shared.b16 {%0,%1,%2,%3}, [%4];"
        : "=r"(r0), "=r"(r1), "=r"(r2), "=r"(r3) : "r"(addr));
}

__device__ __forceinline__ void mma16816(float* d, const unsigned* a, const unsigned* b) {
    asm volatile("mma.sync.aligned.m16n8k16.row.col.f32.bf16.bf16.f32 "
        "{%0,%1,%2,%3}, {%4,%5,%6,%7}, {%8,%9}, {%0,%1,%2,%3};"
        : "+f"(d[0]), "+f"(d[1]), "+f"(d[2]), "+f"(d[3])
        : "r"(a[0]), "r"(a[1]), "r"(a[2]), "r"(a[3]), "r"(b[0]), "r"(b[1]));
}

__device__ __forceinline__ float blockReduceSum(float v) {
    __shared__ float red[32];
    int lane = threadIdx.x & 31, wid = threadIdx.x >> 5;
    #pragma unroll
    for (int o = 16; o > 0; o >>= 1) v += __shfl_down_sync(0xffffffffu, v, o);
    if (lane == 0) red[wid] = v;
    __syncthreads();
    if (wid == 0) {
        v = (lane < ((blockDim.x + 31) >> 5)) ? red[lane] : 0.f;
        #pragma unroll
        for (int o = 16; o > 0; o >>= 1) v += __shfl_down_sync(0xffffffffu, v, o);
    }
    return v;
}

// ---------------- prep kernels ----------------
__global__ void k_zf2(const float* __restrict__ z) {
    __shared__ float t[32][33];
    int b = blockIdx.z;
    int c0 = blockIdx.x * 32;
    int r0 = blockIdx.y * 32;
    const float* src = z + b * DDIM * HWD;
    for (int i = threadIdx.y; i < 32; i += 8)
        t[i][threadIdx.x] = src[(r0 + i) * HWD + c0 + threadIdx.x];
    __syncthreads();
    float* dst = g_zf + b * HWD * DDIM;
    __nv_bfloat16* dstb = g_zbf + b * HWD * DDIM;
    for (int i = threadIdx.y; i < 32; i += 8) {
        float v = t[threadIdx.x][i];
        dst[(c0 + i) * DDIM + r0 + threadIdx.x] = v;
        dstb[(c0 + i) * DDIM + r0 + threadIdx.x] = __float2bfloat16(v);
    }
}

__global__ void k_zsq() {
    int r = blockIdx.x;
    float v = g_zf[r * DDIM + threadIdx.x];
    v *= v;
    v = blockReduceSum(v);
    if (threadIdx.x == 0) g_zsq[r] = v;
}

__global__ void k_wsq2(const float* __restrict__ w) {
    int r = blockIdx.x;
    float v0 = w[r * DDIM + threadIdx.x];
    g_wbf[r * DDIM + threadIdx.x] = __float2bfloat16(v0);
    float v = v0 * v0;
    v = blockReduceSum(v);
    if (threadIdx.x == 0) g_wsq[r] = v;
}

__global__ void k_zero() {
    int i = blockIdx.x * blockDim.x + threadIdx.x;
    if (i < KCB * DDIM) g_esum[i] = 0.f;
    if (i < KCB) g_counts[i] = 0.f;
    if (i < 8) g_scal[i] = 0.f;
}

// ---------------- bf16 mma.sync screen (256 threads, 8 warps, warp tile 64x32) ----------------
#define SROW 528
#define ABYTES (128 * SROW)
#define BOFF   ABYTES
#define BSZ    ABYTES
#define RMIN_OFF (3 * ABYTES)
#define SCR_SMEM (3 * ABYTES + 512)
#define STHR 256

__device__ __forceinline__ void load_tile_scr(char* dst, const char* gsrc, int tid) {
    #pragma unroll
    for (int it = 0; it < 16; it++) {
        int j = tid + it * STHR;
        int r = j >> 5, e = j & 31;
        cp_async16(dst + r * SROW + e * 16, gsrc + (size_t)r * 512 + e * 16);
    }
}

__global__ void __launch_bounds__(STHR, 1) k_screen() {
    extern __shared__ char sm[];
    unsigned sb = (unsigned)__cvta_generic_to_shared(sm);
    unsigned* s_rmin = (unsigned*)(sm + RMIN_OFF);
    int tid = threadIdx.x, lane = tid & 31, wid = tid >> 5;
    int wm = wid >> 2, wn = wid & 3;      // 2x4 warp grid; warp tile 64x32
    int gm0 = blockIdx.x * 128;
    int quad = lane & 3;

    if (tid < 128) s_rmin[tid] = 0x7f800000u;

    load_tile_scr(sm, (const char*)g_zbf + (size_t)gm0 * 512, tid);
    load_tile_scr(sm + BOFF, (const char*)g_wbf, tid);
    CP_COMMIT();

    int trow[8]; float zq[8]; float rmin[8]; int cnt[8];
    #pragma unroll
    for (int mt = 0; mt < 4; mt++)
        #pragma unroll
        for (int h = 0; h < 2; h++) {
            int s = mt * 2 + h;
            trow[s] = wm * 64 + mt * 16 + h * 8 + (lane >> 2);
            zq[s] = g_zsq[gm0 + trow[s]];
            rmin[s] = __int_as_float(0x7f800000);
            cnt[s] = 0;
        }

    unsigned a_off = (unsigned)((wm * 64 + (lane & 15)) * SROW + ((lane >> 4) * 8) * 2);
    unsigned b_off = (unsigned)((wn * 32 + ((lane >> 4) & 1) * 8 + (lane & 7)) * SROW
                                + (((lane >> 3) & 1) * 8) * 2);

    #pragma unroll 1
    for (int cb = 0; cb < 128; cb++) {
        if (cb + 1 < 128) {
            load_tile_scr(sm + BOFF + ((cb + 1) & 1) * BSZ,
                          (const char*)g_wbf + (size_t)(cb + 1) * 128 * 512, tid);
            CP_COMMIT();
            asm volatile("cp.async.wait_group 1;");
        } else {
            asm volatile("cp.async.wait_group 0;");
        }
        __syncthreads();

        float acc[4][4][4];
        #pragma unroll
        for (int mt = 0; mt < 4; mt++)
            #pragma unroll
            for (int nt = 0; nt < 4; nt++)
                #pragma unroll
                for (int r = 0; r < 4; r++) acc[mt][nt][r] = 0.f;

        unsigned bb = sb + BOFF + (cb & 1) * BSZ;

        #pragma unroll
        for (int kc = 0; kc < 16; kc++) {
            unsigned a[4][4], b[4][2];
            #pragma unroll
            for (int mt = 0; mt < 4; mt++)
                ldsm_x4(sb + a_off + mt * 16 * SROW + kc * 32,
                        a[mt][0], a[mt][1], a[mt][2], a[mt][3]);
            #pragma unroll
            for (int hf = 0; hf < 2; hf++) {
                unsigned r0, r1, r2, r3;
                ldsm_x4(bb + b_off + hf * 16 * SROW + kc * 32, r0, r1, r2, r3);
                b[hf * 2][0] = r0; b[hf * 2][1] = r1;
                b[hf * 2 + 1][0] = r2; b[hf * 2 + 1][1] = r3;
            }
            #pragma unroll
            for (int mt = 0; mt < 4; mt++)
                #pragma unroll
                for (int nt = 0; nt < 4; nt++)
                    mma16816(acc[mt][nt], a[mt], b[nt]);
        }
        __syncthreads();

        // ---- lean epilogue ----
        // hoisted wsq loads (uniform per thread per chunk)
        float w0a[4], w1a[4];
        #pragma unroll
        for (int nt = 0; nt < 4; nt++) {
            int kg = cb * 128 + wn * 32 + nt * 8 + quad * 2;
            w0a[nt] = __ldg(g_wsq + kg);
            w1a[nt] = __ldg(g_wsq + kg + 1);
        }
        int npass = (cb == 0) ? 2 : 1;
        for (int pass = 0; pass < npass; pass++) {
            bool capture = (pass == npass - 1);
            if (cb == 0 && pass == 1) __syncthreads();
            #pragma unroll
            for (int s = 0; s < 8; s++) {
                int mt = s >> 1, h = s & 1;
                float curv = fminf(rmin[s], __uint_as_float(s_rmin[trow[s]]));
                // dot-space threshold: capture iff t + zq <= curv + MARGIN
                float thr = curv + MARGIN - zq[s];
                float vm = __int_as_float(0x7f800000);
                #pragma unroll
                for (int nt = 0; nt < 4; nt++) {
                    float t0 = fmaf(-2.f, acc[mt][nt][h * 2 + 0], w0a[nt]);
                    float t1 = fmaf(-2.f, acc[mt][nt][h * 2 + 1], w1a[nt]);
                    vm = fminf(vm, fminf(t0, t1));
                }
                if (capture && vm <= thr) {   // rare
                    int tokg = gm0 + trow[s];
                    int base = ((tokg * 4 + wn) * 4 + quad) * CAPQ;
                    #pragma unroll
                    for (int nt = 0; nt < 4; nt++) {
                        int kg = cb * 128 + wn * 32 + nt * 8 + quad * 2;
                        float t0 = fmaf(-2.f, acc[mt][nt][h * 2 + 0], w0a[nt]);
                        float t1 = fmaf(-2.f, acc[mt][nt][h * 2 + 1], w1a[nt]);
                        if (t0 <= thr) { if (cnt[s] < CAPQ) g_cand[base + cnt[s]] = kg; cnt[s]++; }
                        if (t1 <= thr) { if (cnt[s] < CAPQ) g_cand[base + cnt[s]] = kg + 1; cnt[s]++; }
                    }
                }
                // d-space running min, quad-reduced; atomic only on improvement
                float vmd = vm + zq[s];
                float nc = fminf(curv, vmd);
                nc = fminf(nc, __shfl_xor_sync(0xffffffffu, nc, 1));
                nc = fminf(nc, __shfl_xor_sync(0xffffffffu, nc, 2));
                rmin[s] = nc;
                if (quad == 0 && nc < curv)
                    atomicMin(&s_rmin[trow[s]], __float_as_uint(nc));
            }
        }
    }
    #pragma unroll
    for (int s = 0; s < 8; s++)
        g_ccnt[((gm0 + trow[s]) * 4 + (wid & 3)) * 4 + quad] = cnt[s];
}

// ---------------- exact fp32 rescue (warp per token, coalesced dots) ----------------
__global__ void __launch_bounds__(256) k_rescue(const float* __restrict__ w) {
    __shared__ int s_list[8][NSUB * CAPQ];
    int warp = threadIdx.x >> 5, lane = threadIdx.x & 31;
    int n = blockIdx.x * 8 + warp;

    int myc = (lane < NSUB) ? g_ccnt[n * NSUB + lane] : 0;
    unsigned ovmask = __ballot_sync(0xffffffffu, myc > CAPQ);
    if (ovmask) return;   // handled by k_rescue_ov (rare)

    int p = myc;
    #pragma unroll
    for (int o = 1; o < 32; o <<= 1) {
        int t = __shfl_up_sync(0xffffffffu, p, o);
        if (lane >= o) p += t;
    }
    int base = p - myc;
    int total = __shfl_sync(0xffffffffu, p, 31);
    const int* lst = g_cand + (n * NSUB + lane) * CAPQ;
    for (int i = 0; i < myc; i++) s_list[warp][base + i] = lst[i];
    __syncwarp();

    const float4* zr4 = (const float4*)(g_zf + (size_t)n * DDIM);
    float4 zv0 = zr4[lane], zv1 = zr4[lane + 32];
    float zqv = g_zsq[n];
    unsigned long long best = ~0ull;

    for (int ci = 0; ci < total; ci++) {
        int k = s_list[warp][ci];
        const float4* wr4 = (const float4*)(w + (size_t)k * DDIM);
        float4 wv0 = __ldg(wr4 + lane), wv1 = __ldg(wr4 + lane + 32);
        float dot = 0.f;
        dot = fmaf(zv0.x, wv0.x, dot); dot = fmaf(zv0.y, wv0.y, dot);
        dot = fmaf(zv0.z, wv0.z, dot); dot = fmaf(zv0.w, wv0.w, dot);
        dot = fmaf(zv1.x, wv1.x, dot); dot = fmaf(zv1.y, wv1.y, dot);
        dot = fmaf(zv1.z, wv1.z, dot); dot = fmaf(zv1.w, wv1.w, dot);
        #pragma unroll
        for (int o = 16; o > 0; o >>= 1) dot += __shfl_xor_sync(0xffffffffu, dot, o);
        float v = __fsub_rn(__fadd_rn(zqv, g_wsq[k]), 2.0f * dot);
        unsigned long long key = ((unsigned long long)__float_as_uint(v) << 32) | (unsigned)k;
        if (key < best) best = key;
    }
    if (lane == 0) g_token[n] = (int)(best & 0xffffffffull);
}

// deterministic full scan for (rare) overflow tokens — cheap early-out
__global__ void k_rescue_ov(const float* __restrict__ w) {
    int n = blockIdx.x;
    __shared__ int ovf;
    if (threadIdx.x == 0) ovf = 0;
    __syncthreads();
    if (threadIdx.x < NSUB && g_ccnt[n * NSUB + threadIdx.x] > CAPQ) ovf = 1;
    __syncthreads();
    if (!ovf) return;

    __shared__ unsigned long long sbm[256];
    const float4* zr4 = (const float4*)(g_zf + (size_t)n * DDIM);
    float zqv = g_zsq[n];
    unsigned long long best = ~0ull;
    for (int k = threadIdx.x; k < KCB; k += 256) {
        const float4* wr4 = (const float4*)(w + (size_t)k * DDIM);
        float dot = 0.f;
        #pragma unroll 8
        for (int d4 = 0; d4 < 64; d4++) {
            float4 wv = __ldg(wr4 + d4);
            float4 zv = zr4[d4];
            dot = fmaf(zv.x, wv.x, dot);
            dot = fmaf(zv.y, wv.y, dot);
            dot = fmaf(zv.z, wv.z, dot);
            dot = fmaf(zv.w, wv.w, dot);
        }
        float v = __fsub_rn(__fadd_rn(zqv, g_wsq[k]), 2.0f * dot);
        unsigned long long key = ((unsigned long long)__float_as_uint(v) << 32) | (unsigned)k;
        if (key < best) best = key;
    }
    sbm[threadIdx.x] = best;
    __syncthreads();
    for (int s = 128; s > 0; s >>= 1) {
        if (threadIdx.x < s && sbm[threadIdx.x + s] < sbm[threadIdx.x])
            sbm[threadIdx.x] = sbm[threadIdx.x + s];
        __syncthreads();
    }
    if (threadIdx.x == 0) g_token[n] = (int)(sbm[0] & 0xffffffffull);
}

// ---------------- EMA / stats / output kernels ----------------
__global__ void k_scatter() {
    int n = blockIdx.x;
    int t = g_token[n];
    if (threadIdx.x == 0) atomicAdd(&g_counts[t], 1.0f);
    const float* src = g_zf + n * DDIM;
    float* dst = g_esum + t * DDIM;
    for (int d = threadIdx.x; d < DDIM; d += blockDim.x)
        atomicAdd(&dst[d], src[d]);
}

__global__ void k_cluster(const float* __restrict__ cs, float* __restrict__ ocn) {
    int k = blockIdx.x * 256 + threadIdx.x;
    float cnt = g_counts[k];
    float cn = 0.8f * cs[k] + 0.2f * cnt;
    ocn[k] = cn;
    float nz = (cnt > 0.f) ? 1.f : 0.f;
    float s_cn = cn, s_cnt = cnt, s_nz = nz;
    #pragma unroll
    for (int o = 16; o > 0; o >>= 1) {
        s_cn  += __shfl_down_sync(0xffffffffu, s_cn, o);
        s_cnt += __shfl_down_sync(0xffffffffu, s_cnt, o);
        s_nz  += __shfl_down_sync(0xffffffffu, s_nz, o);
    }
    if ((threadIdx.x & 31) == 0) {
        atomicAdd(&g_scal[1], s_cn);
        atomicAdd(&g_scal[2], s_cnt);
        atomicAdd(&g_scal[3], s_nz);
    }
}

__global__ void k_ema(const float* __restrict__ ea, float* __restrict__ oea) {
    int i = blockIdx.x * 256 + threadIdx.x;
    oea[i] = 0.8f * ea[i] + 0.2f * g_esum[i];
}

__global__ void k_entropy() {
    int k = blockIdx.x * 256 + threadIdx.x;
    float cnt = g_counts[k];
    float sumc = g_scal[2];
    float p = cnt / sumc;
    float term = p * logf(p + 1e-10f);
    #pragma unroll
    for (int o = 16; o > 0; o >>= 1) term += __shfl_down_sync(0xffffffffu, term, o);
    if ((threadIdx.x & 31) == 0) atomicAdd(&g_scal[4], term);
}

__global__ void k_weight(const float* __restrict__ ocn, const float* __restrict__ oea,
                         float* __restrict__ ow) {
    int i = blockIdx.x * 256 + threadIdx.x;
    int k = i >> 8;
    float cn = ocn[k];
    float n = g_scal[1];
    float t = (cn + 1e-5f) / (n + 0.16384f);
    float smv = t * n;
    ow[i] = oea[i] / smv;
}

__global__ void k_outloss(const float* __restrict__ z, const float* __restrict__ w,
                          float* __restrict__ oout) {
    int idx = blockIdx.x * 256 + threadIdx.x;
    int b = idx >> 18;
    int c = (idx >> 10) & 255;
    int p = idx & 1023;
    int n = (b << 10) | p;
    float zt = z[idx];
    float zqv = __ldg(&w[g_token[n] * DDIM + c]);
    float diff = __fsub_rn(zqv, zt);
    oout[idx] = __fadd_rn(zt, diff);
    float sq = diff * diff;
    sq = blockReduceSum(sq);
    if (threadIdx.x == 0) atomicAdd(&g_scal[0], sq);
}

__global__ void k_scalars(float* __restrict__ o) {
    float S = g_scal[0];
    o[0] = 0.25f * (S / 4194304.0f);
    o[1] = S / 16384.0f;
    o[2] = g_scal[3] / 16384.0f;
    o[3] = expf(-g_scal[4]);
}

// ---------------- launch ----------------
extern "C" void kernel_launch(void* const* d_in, const int* in_sizes, int n_in,
                              void* d_out, int out_size) {
    const float* z  = (const float*)d_in[0];
    const float* w  = (const float*)d_in[1];
    const float* cs = (const float*)d_in[2];
    const float* ea = (const float*)d_in[3];
    float* out = (float*)d_out;

    float* o_out  = out + O_OUT;
    float* o_scal = out + O_SCAL;
    float* o_wnew = out + O_WNEW;
    float* o_cnew = out + O_CNEW;
    float* o_ea   = out + O_EANEW;

    cudaFuncSetAttribute(k_screen, cudaFuncAttributeMaxDynamicSharedMemorySize, SCR_SMEM);

    k_zf2<<<dim3(32, 8, NBATCH), dim3(32, 8)>>>(z);   // launch 0
    k_zsq<<<N_TOK, 256>>>();                          // launch 1
    k_wsq2<<<KCB, 256>>>(w);                          // launch 2
    k_screen<<<N_TOK / 128, STHR, SCR_SMEM>>>();      // launch 3  (profiled slot)
    k_zero<<<(KCB * DDIM + 255) / 256, 256>>>();
    k_rescue<<<N_TOK / 8, 256>>>(w);
    k_rescue_ov<<<N_TOK, 256>>>(w);
    k_scatter<<<N_TOK, 128>>>();
    k_cluster<<<KCB / 256, 256>>>(cs, o_cnew);
    k_ema<<<(KCB * DDIM) / 256, 256>>>(ea, o_ea);
    k_entropy<<<KCB / 256, 256>>>();
    k_weight<<<(KCB * DDIM) / 256, 256>>>(o_cnew, o_ea, o_wnew);
    k_outloss<<<(NBATCH * DDIM * HWD) / 256, 256>>>(z, w, o_out);
    k_scalars<<<1, 1>>>(o_scal);
}

// round 13
// speedup vs baseline: 1.4970x; 1.4970x over previous
#include <cuda_runtime.h>
#include <cuda_bf16.h>
#include <math.h>

// ---------------- problem constants ----------------
#define N_TOK 16384
#define KCB   16384
#define DDIM  256
#define NBATCH 16
#define HWD   1024

#define O_OUT   0
#define O_SCAL  4194304
#define O_WNEW  4194308
#define O_CNEW  8388612
#define O_EANEW 8404996

#define CAPQ   16
#define NSUB   16
#define MARGIN 1e-3f

// ---------------- device scratch ----------------
__device__ float g_zf[N_TOK * DDIM];
__device__ float g_wsq[KCB];
__device__ float g_zsq[N_TOK];
__device__ int   g_token[N_TOK];
__device__ float g_counts[KCB];
__device__ float g_esum[KCB * DDIM];
__device__ float g_scal[8];
__device__ __nv_bfloat16 g_zbf[N_TOK * DDIM];
__device__ __nv_bfloat16 g_wbf[KCB * DDIM];
__device__ int g_cand[N_TOK * NSUB * CAPQ];
__device__ int g_ccnt[N_TOK * NSUB];

// ---------------- helpers ----------------
__device__ __forceinline__ void cp_async16(void* smem_dst, const void* gsrc) {
    unsigned sa = (unsigned)__cvta_generic_to_shared(smem_dst);
    asm volatile("cp.async.cg.shared.global [%0], [%1], 16;" :: "r"(sa), "l"(gsrc));
}
#define CP_COMMIT() asm volatile("cp.async.commit_group;")

__device__ __forceinline__ void ldsm_x4(unsigned addr, unsigned& r0, unsigned& r1,
                                        unsigned& r2, unsigned& r3) {
    asm volatile("ldmatrix.sync.aligned.m8n8.x4.shared.b16 {%0,%1,%2,%3}, [%4];"
        : "=r"(r0), "=r"(r1), "=r"(r2), "=r"(r3) : "r"(addr));
}

__device__ __forceinline__ void mma16816(float* d, const unsigned* a, const unsigned* b) {
    asm volatile("mma.sync.aligned.m16n8k16.row.col.f32.bf16.bf16.f32 "
        "{%0,%1,%2,%3}, {%4,%5,%6,%7}, {%8,%9}, {%0,%1,%2,%3};"
        : "+f"(d[0]), "+f"(d[1]), "+f"(d[2]), "+f"(d[3])
        : "r"(a[0]), "r"(a[1]), "r"(a[2]), "r"(a[3]), "r"(b[0]), "r"(b[1]));
}

__device__ __forceinline__ float blockReduceSum(float v) {
    __shared__ float red[32];
    int lane = threadIdx.x & 31, wid = threadIdx.x >> 5;
    #pragma unroll
    for (int o = 16; o > 0; o >>= 1) v += __shfl_down_sync(0xffffffffu, v, o);
    if (lane == 0) red[wid] = v;
    __syncthreads();
    if (wid == 0) {
        v = (lane < ((blockDim.x + 31) >> 5)) ? red[lane] : 0.f;
        #pragma unroll
        for (int o = 16; o > 0; o >>= 1) v += __shfl_down_sync(0xffffffffu, v, o);
    }
    return v;
}

// ---------------- prep kernels ----------------
__global__ void k_zf2(const float* __restrict__ z) {
    __shared__ float t[32][33];
    int b = blockIdx.z;
    int c0 = blockIdx.x * 32;
    int r0 = blockIdx.y * 32;
    const float* src = z + b * DDIM * HWD;
    for (int i = threadIdx.y; i < 32; i += 8)
        t[i][threadIdx.x] = src[(r0 + i) * HWD + c0 + threadIdx.x];
    __syncthreads();
    float* dst = g_zf + b * HWD * DDIM;
    __nv_bfloat16* dstb = g_zbf + b * HWD * DDIM;
    for (int i = threadIdx.y; i < 32; i += 8) {
        float v = t[threadIdx.x][i];
        dst[(c0 + i) * DDIM + r0 + threadIdx.x] = v;
        dstb[(c0 + i) * DDIM + r0 + threadIdx.x] = __float2bfloat16(v);
    }
}

__global__ void k_zsq() {
    int r = blockIdx.x;
    float v = g_zf[r * DDIM + threadIdx.x];
    v *= v;
    v = blockReduceSum(v);
    if (threadIdx.x == 0) g_zsq[r] = v;
}

__global__ void k_wsq2(const float* __restrict__ w) {
    int r = blockIdx.x;
    float v0 = w[r * DDIM + threadIdx.x];
    g_wbf[r * DDIM + threadIdx.x] = __float2bfloat16(v0);
    float v = v0 * v0;
    v = blockReduceSum(v);
    if (threadIdx.x == 0) g_wsq[r] = v;
}

__global__ void k_zero() {
    int i = blockIdx.x * blockDim.x + threadIdx.x;
    if (i < KCB * DDIM) g_esum[i] = 0.f;
    if (i < KCB) g_counts[i] = 0.f;
    if (i < 8) g_scal[i] = 0.f;
}

// ---------------- bf16 mma.sync screen ----------------
// 2 CTAs/SM. CTA: 64 tokens; B streamed as 128-code x 128-k half-tiles (k-split),
// double-buffered. 8 warps (2x4), warp tile 32x32 (R11-proven fragment layout).
#define SROW 528                   // A row pitch (256 bf16 + pad)
#define BROW 272                   // B half-row pitch (128 bf16 + pad)
#define A_BYTES (64 * SROW)        // 33792
#define B_BYTES (128 * BROW)       // 34816
#define B0_OFF  A_BYTES
#define B1_OFF  (A_BYTES + B_BYTES)
#define RMIN_OFF (A_BYTES + 2 * B_BYTES)     // 103424
#define SCR_SMEM (RMIN_OFF + 256)            // 103680
#define STHR 256

// A tile: 64 rows x 512B
__device__ __forceinline__ void load_tile_A(char* dst, const char* gsrc, int tid) {
    #pragma unroll
    for (int it = 0; it < 8; it++) {
        int j = tid + it * STHR;
        int r = j >> 5, e = j & 31;
        cp_async16(dst + r * SROW + e * 16, gsrc + (size_t)r * 512 + e * 16);
    }
}

// B half-tile: 128 code-rows x 256B (k-half)
__device__ __forceinline__ void load_tile_B(char* dst, int cb, int half, int tid) {
    const char* gsrc = (const char*)g_wbf + (size_t)cb * 128 * 512 + half * 256;
    #pragma unroll
    for (int it = 0; it < 8; it++) {
        int j = tid + it * STHR;
        int r = j >> 4, e = j & 15;
        cp_async16(dst + r * BROW + e * 16, gsrc + (size_t)r * 512 + e * 16);
    }
}

__global__ void __launch_bounds__(STHR, 2) k_screen() {
    extern __shared__ char sm[];
    unsigned sb = (unsigned)__cvta_generic_to_shared(sm);
    unsigned* s_rmin = (unsigned*)(sm + RMIN_OFF);
    int tid = threadIdx.x, lane = tid & 31, wid = tid >> 5;
    int wm = wid >> 2, wn = wid & 3;      // 2x4 grid; warp tile 32x32
    int gm0 = blockIdx.x * 64;
    int quad = lane & 3;

    if (tid < 64) s_rmin[tid] = 0x7f800000u;

    load_tile_A(sm, (const char*)g_zbf + (size_t)gm0 * 512, tid);
    load_tile_B(sm + B0_OFF, 0, 0, tid);
    CP_COMMIT();

    int trow[4]; float zq[4]; float rmin[4]; int cnt[4];
    #pragma unroll
    for (int mt = 0; mt < 2; mt++)
        #pragma unroll
        for (int h = 0; h < 2; h++) {
            int s = mt * 2 + h;
            trow[s] = wm * 32 + mt * 16 + h * 8 + (lane >> 2);
            zq[s] = g_zsq[gm0 + trow[s]];
            rmin[s] = __int_as_float(0x7f800000);
            cnt[s] = 0;
        }

    unsigned a_off = (unsigned)((wm * 32 + (lane & 15)) * SROW + ((lane >> 4) * 8) * 2);
    unsigned b_off = (unsigned)((wn * 32 + ((lane >> 4) & 1) * 8 + (lane & 7)) * BROW
                                + (((lane >> 3) & 1) * 8) * 2);

    float acc[2][4][4];

    #pragma unroll 1
    for (int hh = 0; hh < 256; hh++) {       // 128 chunks x 2 k-halves
        int cb = hh >> 1, half = hh & 1;
        if (hh + 1 < 256) {
            load_tile_B(sm + ((hh + 1) & 1 ? B1_OFF : B0_OFF), (hh + 1) >> 1, (hh + 1) & 1, tid);
            CP_COMMIT();
            asm volatile("cp.async.wait_group 1;");
        } else {
            asm volatile("cp.async.wait_group 0;");
        }
        __syncthreads();

        if (half == 0) {
            #pragma unroll
            for (int mt = 0; mt < 2; mt++)
                #pragma unroll
                for (int nt = 0; nt < 4; nt++)
                    #pragma unroll
                    for (int r = 0; r < 4; r++) acc[mt][nt][r] = 0.f;
        }

        unsigned bb = sb + ((hh & 1) ? B1_OFF : B0_OFF);
        #pragma unroll
        for (int kk = 0; kk < 8; kk++) {
            int kc = half * 8 + kk;          // global k-chunk for A
            unsigned a[2][4], b[4][2];
            #pragma unroll
            for (int mt = 0; mt < 2; mt++)
                ldsm_x4(sb + a_off + mt * 16 * SROW + kc * 32,
                        a[mt][0], a[mt][1], a[mt][2], a[mt][3]);
            #pragma unroll
            for (int hf = 0; hf < 2; hf++) {
                unsigned r0, r1, r2, r3;
                ldsm_x4(bb + b_off + hf * 16 * BROW + kk * 32, r0, r1, r2, r3);
                b[hf * 2][0] = r0; b[hf * 2][1] = r1;
                b[hf * 2 + 1][0] = r2; b[hf * 2 + 1][1] = r3;
            }
            #pragma unroll
            for (int mt = 0; mt < 2; mt++)
                #pragma unroll
                for (int nt = 0; nt < 4; nt++)
                    mma16816(acc[mt][nt], a[mt], b[nt]);
        }

        if (half == 1) {
            // epilogue (R11 structure)
            int npass = (cb == 0) ? 2 : 1;
            for (int pass = 0; pass < npass; pass++) {
                bool capture = (pass == npass - 1);
                if (cb == 0 && pass == 1) __syncthreads();
                float cur[4];
                #pragma unroll
                for (int s = 0; s < 4; s++)
                    cur[s] = fminf(rmin[s], __uint_as_float(s_rmin[trow[s]]));
                #pragma unroll
                for (int nt = 0; nt < 4; nt++) {
                    int kg = cb * 128 + wn * 32 + nt * 8 + quad * 2;
                    float w0 = __ldg(g_wsq + kg), w1 = __ldg(g_wsq + kg + 1);
                    #pragma unroll
                    for (int mt = 0; mt < 2; mt++)
                        #pragma unroll
                        for (int h = 0; h < 2; h++) {
                            int s = mt * 2 + h;
                            float v0 = fmaf(-2.f, acc[mt][nt][h * 2 + 0], zq[s] + w0);
                            float v1 = fmaf(-2.f, acc[mt][nt][h * 2 + 1], zq[s] + w1);
                            if (capture) {
                                int tokg = gm0 + trow[s];
                                if (v0 <= cur[s] + MARGIN) {
                                    if (cnt[s] < CAPQ)
                                        g_cand[((tokg * 4 + wn) * 4 + quad) * CAPQ + cnt[s]] = kg;
                                    cnt[s]++;
                                }
                                if (v1 <= cur[s] + MARGIN) {
                                    if (cnt[s] < CAPQ)
                                        g_cand[((tokg * 4 + wn) * 4 + quad) * CAPQ + cnt[s]] = kg + 1;
                                    cnt[s]++;
                                }
                            }
                            cur[s] = fminf(cur[s], fminf(v0, v1));
                        }
                }
                #pragma unroll
                for (int s = 0; s < 4; s++) {
                    rmin[s] = cur[s];
                    atomicMin(&s_rmin[trow[s]], __float_as_uint(cur[s]));
                }
            }
        }
        __syncthreads();
    }
    #pragma unroll
    for (int s = 0; s < 4; s++)
        g_ccnt[((gm0 + trow[s]) * 4 + wn) * 4 + quad] = cnt[s];
}

// ---------------- exact fp32 rescue (warp per token, coalesced dots) ----------------
__global__ void __launch_bounds__(256) k_rescue(const float* __restrict__ w) {
    __shared__ int s_list[8][NSUB * CAPQ];
    int warp = threadIdx.x >> 5, lane = threadIdx.x & 31;
    int n = blockIdx.x * 8 + warp;

    int myc = (lane < NSUB) ? g_ccnt[n * NSUB + lane] : 0;
    unsigned ovmask = __ballot_sync(0xffffffffu, myc > CAPQ);
    if (ovmask) return;   // handled by k_rescue_ov (rare)

    int p = myc;
    #pragma unroll
    for (int o = 1; o < 32; o <<= 1) {
        int t = __shfl_up_sync(0xffffffffu, p, o);
        if (lane >= o) p += t;
    }
    int base = p - myc;
    int total = __shfl_sync(0xffffffffu, p, 31);
    const int* lst = g_cand + (n * NSUB + lane) * CAPQ;
    for (int i = 0; i < myc; i++) s_list[warp][base + i] = lst[i];
    __syncwarp();

    const float4* zr4 = (const float4*)(g_zf + (size_t)n * DDIM);
    float4 zv0 = zr4[lane], zv1 = zr4[lane + 32];
    float zqv = g_zsq[n];
    unsigned long long best = ~0ull;

    for (int ci = 0; ci < total; ci++) {
        int k = s_list[warp][ci];
        const float4* wr4 = (const float4*)(w + (size_t)k * DDIM);
        float4 wv0 = __ldg(wr4 + lane), wv1 = __ldg(wr4 + lane + 32);
        float dot = 0.f;
        dot = fmaf(zv0.x, wv0.x, dot); dot = fmaf(zv0.y, wv0.y, dot);
        dot = fmaf(zv0.z, wv0.z, dot); dot = fmaf(zv0.w, wv0.w, dot);
        dot = fmaf(zv1.x, wv1.x, dot); dot = fmaf(zv1.y, wv1.y, dot);
        dot = fmaf(zv1.z, wv1.z, dot); dot = fmaf(zv1.w, wv1.w, dot);
        #pragma unroll
        for (int o = 16; o > 0; o >>= 1) dot += __shfl_xor_sync(0xffffffffu, dot, o);
        float v = __fsub_rn(__fadd_rn(zqv, g_wsq[k]), 2.0f * dot);
        unsigned long long key = ((unsigned long long)__float_as_uint(v) << 32) | (unsigned)k;
        if (key < best) best = key;
    }
    if (lane == 0) g_token[n] = (int)(best & 0xffffffffull);
}

// deterministic full scan for (rare) overflow tokens — cheap early-out
__global__ void k_rescue_ov(const float* __restrict__ w) {
    int n = blockIdx.x;
    __shared__ int ovf;
    if (threadIdx.x == 0) ovf = 0;
    __syncthreads();
    if (threadIdx.x < NSUB && g_ccnt[n * NSUB + threadIdx.x] > CAPQ) ovf = 1;
    __syncthreads();
    if (!ovf) return;

    __shared__ unsigned long long sbm[256];
    const float4* zr4 = (const float4*)(g_zf + (size_t)n * DDIM);
    float zqv = g_zsq[n];
    unsigned long long best = ~0ull;
    for (int k = threadIdx.x; k < KCB; k += 256) {
        const float4* wr4 = (const float4*)(w + (size_t)k * DDIM);
        float dot = 0.f;
        #pragma unroll 8
        for (int d4 = 0; d4 < 64; d4++) {
            float4 wv = __ldg(wr4 + d4);
            float4 zv = zr4[d4];
            dot = fmaf(zv.x, wv.x, dot);
            dot = fmaf(zv.y, wv.y, dot);
            dot = fmaf(zv.z, wv.z, dot);
            dot = fmaf(zv.w, wv.w, dot);
        }
        float v = __fsub_rn(__fadd_rn(zqv, g_wsq[k]), 2.0f * dot);
        unsigned long long key = ((unsigned long long)__float_as_uint(v) << 32) | (unsigned)k;
        if (key < best) best = key;
    }
    sbm[threadIdx.x] = best;
    __syncthreads();
    for (int s = 128; s > 0; s >>= 1) {
        if (threadIdx.x < s && sbm[threadIdx.x + s] < sbm[threadIdx.x])
            sbm[threadIdx.x] = sbm[threadIdx.x + s];
        __syncthreads();
    }
    if (threadIdx.x == 0) g_token[n] = (int)(sbm[0] & 0xffffffffull);
}

// ---------------- EMA / stats / output kernels ----------------
__global__ void k_scatter() {
    int n = blockIdx.x;
    int t = g_token[n];
    if (threadIdx.x == 0) atomicAdd(&g_counts[t], 1.0f);
    const float* src = g_zf + n * DDIM;
    float* dst = g_esum + t * DDIM;
    for (int d = threadIdx.x; d < DDIM; d += blockDim.x)
        atomicAdd(&dst[d], src[d]);
}

__global__ void k_cluster(const float* __restrict__ cs, float* __restrict__ ocn) {
    int k = blockIdx.x * 256 + threadIdx.x;
    float cnt = g_counts[k];
    float cn = 0.8f * cs[k] + 0.2f * cnt;
    ocn[k] = cn;
    float nz = (cnt > 0.f) ? 1.f : 0.f;
    float s_cn = cn, s_cnt = cnt, s_nz = nz;
    #pragma unroll
    for (int o = 16; o > 0; o >>= 1) {
        s_cn  += __shfl_down_sync(0xffffffffu, s_cn, o);
        s_cnt += __shfl_down_sync(0xffffffffu, s_cnt, o);
        s_nz  += __shfl_down_sync(0xffffffffu, s_nz, o);
    }
    if ((threadIdx.x & 31) == 0) {
        atomicAdd(&g_scal[1], s_cn);
        atomicAdd(&g_scal[2], s_cnt);
        atomicAdd(&g_scal[3], s_nz);
    }
}

__global__ void k_ema(const float* __restrict__ ea, float* __restrict__ oea) {
    int i = blockIdx.x * 256 + threadIdx.x;
    oea[i] = 0.8f * ea[i] + 0.2f * g_esum[i];
}

__global__ void k_entropy() {
    int k = blockIdx.x * 256 + threadIdx.x;
    float cnt = g_counts[k];
    float sumc = g_scal[2];
    float p = cnt / sumc;
    float term = p * logf(p + 1e-10f);
    #pragma unroll
    for (int o = 16; o > 0; o >>= 1) term += __shfl_down_sync(0xffffffffu, term, o);
    if ((threadIdx.x & 31) == 0) atomicAdd(&g_scal[4], term);
}

__global__ void k_weight(const float* __restrict__ ocn, const float* __restrict__ oea,
                         float* __restrict__ ow) {
    int i = blockIdx.x * 256 + threadIdx.x;
    int k = i >> 8;
    float cn = ocn[k];
    float n = g_scal[1];
    float t = (cn + 1e-5f) / (n + 0.16384f);
    float smv = t * n;
    ow[i] = oea[i] / smv;
}

__global__ void k_outloss(const float* __restrict__ z, const float* __restrict__ w,
                          float* __restrict__ oout) {
    int idx = blockIdx.x * 256 + threadIdx.x;
    int b = idx >> 18;
    int c = (idx >> 10) & 255;
    int p = idx & 1023;
    int n = (b << 10) | p;
    float zt = z[idx];
    float zqv = __ldg(&w[g_token[n] * DDIM + c]);
    float diff = __fsub_rn(zqv, zt);
    oout[idx] = __fadd_rn(zt, diff);
    float sq = diff * diff;
    sq = blockReduceSum(sq);
    if (threadIdx.x == 0) atomicAdd(&g_scal[0], sq);
}

__global__ void k_scalars(float* __restrict__ o) {
    float S = g_scal[0];
    o[0] = 0.25f * (S / 4194304.0f);
    o[1] = S / 16384.0f;
    o[2] = g_scal[3] / 16384.0f;
    o[3] = expf(-g_scal[4]);
}

// ---------------- launch ----------------
extern "C" void kernel_launch(void* const* d_in, const int* in_sizes, int n_in,
                              void* d_out, int out_size) {
    const float* z  = (const float*)d_in[0];
    const float* w  = (const float*)d_in[1];
    const float* cs = (const float*)d_in[2];
    const float* ea = (const float*)d_in[3];
    float* out = (float*)d_out;

    float* o_out  = out + O_OUT;
    float* o_scal = out + O_SCAL;
    float* o_wnew = out + O_WNEW;
    float* o_cnew = out + O_CNEW;
    float* o_ea   = out + O_EANEW;

    cudaFuncSetAttribute(k_screen, cudaFuncAttributeMaxDynamicSharedMemorySize, SCR_SMEM);

    k_zf2<<<dim3(32, 8, NBATCH), dim3(32, 8)>>>(z);   // launch 0
    k_zsq<<<N_TOK, 256>>>();                          // launch 1
    k_wsq2<<<KCB, 256>>>(w);                          // launch 2
    k_screen<<<N_TOK / 64, STHR, SCR_SMEM>>>();       // launch 3  (profiled slot)
    k_zero<<<(KCB * DDIM + 255) / 256, 256>>>();
    k_rescue<<<N_TOK / 8, 256>>>(w);
    k_rescue_ov<<<N_TOK, 256>>>(w);
    k_scatter<<<N_TOK, 128>>>();
    k_cluster<<<KCB / 256, 256>>>(cs, o_cnew);
    k_ema<<<(KCB * DDIM) / 256, 256>>>(ea, o_ea);
    k_entropy<<<KCB / 256, 256>>>();
    k_weight<<<(KCB * DDIM) / 256, 256>>>(o_cnew, o_ea, o_wnew);
    k_outloss<<<(NBATCH * DDIM * HWD) / 256, 256>>>(z, w, o_out);
    k_scalars<<<1, 1>>>(o_scal);
}

// round 14
// speedup vs baseline: 1.5432x; 1.0308x over previous
#include <cuda_runtime.h>
#include <cuda_bf16.h>
#include <math.h>

// ---------------- problem constants ----------------
#define N_TOK 16384
#define KCB   16384
#define DDIM  256
#define NBATCH 16
#define HWD   1024

#define O_OUT   0
#define O_SCAL  4194304
#define O_WNEW  4194308
#define O_CNEW  8388612
#define O_EANEW 8404996

#define CAPQ   16
#define NSUB   16
#define MARGIN 1e-3f

// ---------------- device scratch ----------------
__device__ float g_zf[N_TOK * DDIM];
__device__ float g_wsq[KCB];
__device__ float g_zsq[N_TOK];
__device__ int   g_token[N_TOK];
__device__ float g_counts[KCB];
__device__ float g_esum[KCB * DDIM];
__device__ float g_scal[8];
__device__ __nv_bfloat16 g_zbf[N_TOK * DDIM];
__device__ __nv_bfloat16 g_wbf[KCB * DDIM];
__device__ int g_cand[N_TOK * NSUB * CAPQ];
__device__ int g_ccnt[N_TOK * NSUB];

// ---------------- helpers ----------------
__device__ __forceinline__ void cp_async16(void* smem_dst, const void* gsrc) {
    unsigned sa = (unsigned)__cvta_generic_to_shared(smem_dst);
    asm volatile("cp.async.cg.shared.global [%0], [%1], 16;" :: "r"(sa), "l"(gsrc));
}
#define CP_COMMIT() asm volatile("cp.async.commit_group;")

__device__ __forceinline__ void ldsm_x4(unsigned addr, unsigned& r0, unsigned& r1,
                                        unsigned& r2, unsigned& r3) {
    asm volatile("ldmatrix.sync.aligned.m8n8.x4.shared.b16 {%0,%1,%2,%3}, [%4];"
        : "=r"(r0), "=r"(r1), "=r"(r2), "=r"(r3) : "r"(addr));
}

__device__ __forceinline__ void mma16816(float* d, const unsigned* a, const unsigned* b) {
    asm volatile("mma.sync.aligned.m16n8k16.row.col.f32.bf16.bf16.f32 "
        "{%0,%1,%2,%3}, {%4,%5,%6,%7}, {%8,%9}, {%0,%1,%2,%3};"
        : "+f"(d[0]), "+f"(d[1]), "+f"(d[2]), "+f"(d[3])
        : "r"(a[0]), "r"(a[1]), "r"(a[2]), "r"(a[3]), "r"(b[0]), "r"(b[1]));
}

__device__ __forceinline__ float blockReduceSum(float v) {
    __shared__ float red[32];
    int lane = threadIdx.x & 31, wid = threadIdx.x >> 5;
    #pragma unroll
    for (int o = 16; o > 0; o >>= 1) v += __shfl_down_sync(0xffffffffu, v, o);
    if (lane == 0) red[wid] = v;
    __syncthreads();
    if (wid == 0) {
        v = (lane < ((blockDim.x + 31) >> 5)) ? red[lane] : 0.f;
        #pragma unroll
        for (int o = 16; o > 0; o >>= 1) v += __shfl_down_sync(0xffffffffu, v, o);
    }
    return v;
}

// ---------------- prep kernels ----------------
__global__ void k_zf2(const float* __restrict__ z) {
    __shared__ float t[32][33];
    int b = blockIdx.z;
    int c0 = blockIdx.x * 32;
    int r0 = blockIdx.y * 32;
    const float* src = z + b * DDIM * HWD;
    for (int i = threadIdx.y; i < 32; i += 8)
        t[i][threadIdx.x] = src[(r0 + i) * HWD + c0 + threadIdx.x];
    __syncthreads();
    float* dst = g_zf + b * HWD * DDIM;
    __nv_bfloat16* dstb = g_zbf + b * HWD * DDIM;
    for (int i = threadIdx.y; i < 32; i += 8) {
        float v = t[threadIdx.x][i];
        dst[(c0 + i) * DDIM + r0 + threadIdx.x] = v;
        dstb[(c0 + i) * DDIM + r0 + threadIdx.x] = __float2bfloat16(v);
    }
}

__global__ void k_zsq() {
    int r = blockIdx.x;
    float v = g_zf[r * DDIM + threadIdx.x];
    v *= v;
    v = blockReduceSum(v);
    if (threadIdx.x == 0) g_zsq[r] = v;
}

__global__ void k_wsq2(const float* __restrict__ w) {
    int r = blockIdx.x;
    float v0 = w[r * DDIM + threadIdx.x];
    g_wbf[r * DDIM + threadIdx.x] = __float2bfloat16(v0);
    float v = v0 * v0;
    v = blockReduceSum(v);
    if (threadIdx.x == 0) g_wsq[r] = v;
}

__global__ void k_zero() {
    int i = blockIdx.x * blockDim.x + threadIdx.x;
    if (i < KCB * DDIM) g_esum[i] = 0.f;
    if (i < KCB) g_counts[i] = 0.f;
    if (i < 8) g_scal[i] = 0.f;
}

// ---------------- bf16 mma.sync screen ----------------
// 2 CTAs/SM. CTA: 64 tokens; chunk = 256 codes, B staged as k-QUARTER tiles
// (256 code-rows x 64 k, 144B pitch), double-buffered. 8 warps (2m x 4n),
// warp tile 32x64 -> 0.047 B/MAC smem traffic; tensor-bound.
#define SROW 528                   // A row pitch (256 bf16 + 16B pad)
#define BROW 144                   // B quarter-row pitch (64 bf16 = 128B + 16B pad)
#define A_BYTES (64 * SROW)        // 33792
#define B_BYTES (256 * BROW)       // 36864
#define B0_OFF  A_BYTES
#define B1_OFF  (A_BYTES + B_BYTES)
#define RMIN_OFF (A_BYTES + 2 * B_BYTES)     // 107520
#define SCR_SMEM (RMIN_OFF + 256)            // 107776
#define STHR 256

// A tile: 64 rows x 512B
__device__ __forceinline__ void load_tile_A(char* dst, const char* gsrc, int tid) {
    #pragma unroll
    for (int it = 0; it < 8; it++) {
        int j = tid + it * STHR;
        int r = j >> 5, e = j & 31;
        cp_async16(dst + r * SROW + e * 16, gsrc + (size_t)r * 512 + e * 16);
    }
}

// B quarter-tile: 256 code-rows x 128B (k-quarter q of chunk cb)
__device__ __forceinline__ void load_tile_B(char* dst, int cb, int q, int tid) {
    const char* gsrc = (const char*)g_wbf + (size_t)cb * 256 * 512 + q * 128;
    #pragma unroll
    for (int it = 0; it < 8; it++) {
        int j = tid + it * STHR;
        int r = j >> 3, e = j & 7;
        cp_async16(dst + r * BROW + e * 16, gsrc + (size_t)r * 512 + e * 16);
    }
}

__global__ void __launch_bounds__(STHR, 2) k_screen() {
    extern __shared__ char sm[];
    unsigned sb = (unsigned)__cvta_generic_to_shared(sm);
    unsigned* s_rmin = (unsigned*)(sm + RMIN_OFF);
    int tid = threadIdx.x, lane = tid & 31, wid = tid >> 5;
    int wm = wid >> 2, wn = wid & 3;      // 2m x 4n; warp tile 32 x 64
    int gm0 = blockIdx.x * 64;
    int quad = lane & 3;

    if (tid < 64) s_rmin[tid] = 0x7f800000u;

    load_tile_A(sm, (const char*)g_zbf + (size_t)gm0 * 512, tid);
    load_tile_B(sm + B0_OFF, 0, 0, tid);
    CP_COMMIT();

    int trow[4]; float zq[4]; float rmin[4]; int cnt[4];
    #pragma unroll
    for (int mt = 0; mt < 2; mt++)
        #pragma unroll
        for (int h = 0; h < 2; h++) {
            int s = mt * 2 + h;
            trow[s] = wm * 32 + mt * 16 + h * 8 + (lane >> 2);
            zq[s] = g_zsq[gm0 + trow[s]];
            rmin[s] = __int_as_float(0x7f800000);
            cnt[s] = 0;
        }

    unsigned a_off = (unsigned)((wm * 32 + (lane & 15)) * SROW + ((lane >> 4) * 8) * 2);
    unsigned b_off = (unsigned)((wn * 64 + ((lane >> 4) & 1) * 8 + (lane & 7)) * BROW
                                + (((lane >> 3) & 1) * 8) * 2);

    float acc[2][8][4];   // 64 regs: 2 m-tiles x 8 n-tiles x 4

    #pragma unroll 1
    for (int hh = 0; hh < 256; hh++) {       // 64 chunks x 4 k-quarters
        int cb = hh >> 2, q = hh & 3;
        if (hh + 1 < 256) {
            load_tile_B(sm + ((hh + 1) & 1 ? B1_OFF : B0_OFF), (hh + 1) >> 2, (hh + 1) & 3, tid);
            CP_COMMIT();
            asm volatile("cp.async.wait_group 1;");
        } else {
            asm volatile("cp.async.wait_group 0;");
        }
        __syncthreads();

        if (q == 0) {
            #pragma unroll
            for (int mt = 0; mt < 2; mt++)
                #pragma unroll
                for (int nt = 0; nt < 8; nt++)
                    #pragma unroll
                    for (int r = 0; r < 4; r++) acc[mt][nt][r] = 0.f;
        }

        unsigned bb = sb + ((hh & 1) ? B1_OFF : B0_OFF);
        #pragma unroll
        for (int kk = 0; kk < 4; kk++) {     // 4 k-chunks of 16 within quarter
            int kc = q * 4 + kk;             // global k-chunk for A
            unsigned a[2][4], b[8][2];
            #pragma unroll
            for (int mt = 0; mt < 2; mt++)
                ldsm_x4(sb + a_off + mt * 16 * SROW + kc * 32,
                        a[mt][0], a[mt][1], a[mt][2], a[mt][3]);
            #pragma unroll
            for (int hf = 0; hf < 4; hf++) {
                unsigned r0, r1, r2, r3;
                ldsm_x4(bb + b_off + hf * 16 * BROW + kk * 32, r0, r1, r2, r3);
                b[hf * 2][0] = r0; b[hf * 2][1] = r1;
                b[hf * 2 + 1][0] = r2; b[hf * 2 + 1][1] = r3;
            }
            #pragma unroll
            for (int mt = 0; mt < 2; mt++)
                #pragma unroll
                for (int nt = 0; nt < 8; nt++)
                    mma16816(acc[mt][nt], a[mt], b[nt]);
        }

        if (q == 3) {
            // epilogue over 256 codes (R11 structure)
            int npass = (cb == 0) ? 2 : 1;
            for (int pass = 0; pass < npass; pass++) {
                bool capture = (pass == npass - 1);
                if (cb == 0 && pass == 1) __syncthreads();
                float cur[4];
                #pragma unroll
                for (int s = 0; s < 4; s++)
                    cur[s] = fminf(rmin[s], __uint_as_float(s_rmin[trow[s]]));
                #pragma unroll
                for (int nt = 0; nt < 8; nt++) {
                    int kg = cb * 256 + wn * 64 + nt * 8 + quad * 2;
                    float w0 = __ldg(g_wsq + kg), w1 = __ldg(g_wsq + kg + 1);
                    #pragma unroll
                    for (int mt = 0; mt < 2; mt++)
                        #pragma unroll
                        for (int h = 0; h < 2; h++) {
                            int s = mt * 2 + h;
                            float v0 = fmaf(-2.f, acc[mt][nt][h * 2 + 0], zq[s] + w0);
                            float v1 = fmaf(-2.f, acc[mt][nt][h * 2 + 1], zq[s] + w1);
                            if (capture) {
                                int tokg = gm0 + trow[s];
                                if (v0 <= cur[s] + MARGIN) {
                                    if (cnt[s] < CAPQ)
                                        g_cand[((tokg * 4 + wn) * 4 + quad) * CAPQ + cnt[s]] = kg;
                                    cnt[s]++;
                                }
                                if (v1 <= cur[s] + MARGIN) {
                                    if (cnt[s] < CAPQ)
                                        g_cand[((tokg * 4 + wn) * 4 + quad) * CAPQ + cnt[s]] = kg + 1;
                                    cnt[s]++;
                                }
                            }
                            cur[s] = fminf(cur[s], fminf(v0, v1));
                        }
                }
                #pragma unroll
                for (int s = 0; s < 4; s++) {
                    rmin[s] = cur[s];
                    atomicMin(&s_rmin[trow[s]], __float_as_uint(cur[s]));
                }
            }
        }
        __syncthreads();
    }
    #pragma unroll
    for (int s = 0; s < 4; s++)
        g_ccnt[((gm0 + trow[s]) * 4 + wn) * 4 + quad] = cnt[s];
}

// ---------------- exact fp32 rescue (warp per token, coalesced dots) ----------------
__global__ void __launch_bounds__(256) k_rescue(const float* __restrict__ w) {
    __shared__ int s_list[8][NSUB * CAPQ];
    int warp = threadIdx.x >> 5, lane = threadIdx.x & 31;
    int n = blockIdx.x * 8 + warp;

    int myc = (lane < NSUB) ? g_ccnt[n * NSUB + lane] : 0;
    unsigned ovmask = __ballot_sync(0xffffffffu, myc > CAPQ);
    if (ovmask) return;   // handled by k_rescue_ov (rare)

    int p = myc;
    #pragma unroll
    for (int o = 1; o < 32; o <<= 1) {
        int t = __shfl_up_sync(0xffffffffu, p, o);
        if (lane >= o) p += t;
    }
    int base = p - myc;
    int total = __shfl_sync(0xffffffffu, p, 31);
    const int* lst = g_cand + (n * NSUB + lane) * CAPQ;
    for (int i = 0; i < myc; i++) s_list[warp][base + i] = lst[i];
    __syncwarp();

    const float4* zr4 = (const float4*)(g_zf + (size_t)n * DDIM);
    float4 zv0 = zr4[lane], zv1 = zr4[lane + 32];
    float zqv = g_zsq[n];
    unsigned long long best = ~0ull;

    for (int ci = 0; ci < total; ci++) {
        int k = s_list[warp][ci];
        const float4* wr4 = (const float4*)(w + (size_t)k * DDIM);
        float4 wv0 = __ldg(wr4 + lane), wv1 = __ldg(wr4 + lane + 32);
        float dot = 0.f;
        dot = fmaf(zv0.x, wv0.x, dot); dot = fmaf(zv0.y, wv0.y, dot);
        dot = fmaf(zv0.z, wv0.z, dot); dot = fmaf(zv0.w, wv0.w, dot);
        dot = fmaf(zv1.x, wv1.x, dot); dot = fmaf(zv1.y, wv1.y, dot);
        dot = fmaf(zv1.z, wv1.z, dot); dot = fmaf(zv1.w, wv1.w, dot);
        #pragma unroll
        for (int o = 16; o > 0; o >>= 1) dot += __shfl_xor_sync(0xffffffffu, dot, o);
        float v = __fsub_rn(__fadd_rn(zqv, g_wsq[k]), 2.0f * dot);
        unsigned long long key = ((unsigned long long)__float_as_uint(v) << 32) | (unsigned)k;
        if (key < best) best = key;
    }
    if (lane == 0) g_token[n] = (int)(best & 0xffffffffull);
}

// deterministic full scan for (rare) overflow tokens — cheap early-out
__global__ void k_rescue_ov(const float* __restrict__ w) {
    int n = blockIdx.x;
    __shared__ int ovf;
    if (threadIdx.x == 0) ovf = 0;
    __syncthreads();
    if (threadIdx.x < NSUB && g_ccnt[n * NSUB + threadIdx.x] > CAPQ) ovf = 1;
    __syncthreads();
    if (!ovf) return;

    __shared__ unsigned long long sbm[256];
    const float4* zr4 = (const float4*)(g_zf + (size_t)n * DDIM);
    float zqv = g_zsq[n];
    unsigned long long best = ~0ull;
    for (int k = threadIdx.x; k < KCB; k += 256) {
        const float4* wr4 = (const float4*)(w + (size_t)k * DDIM);
        float dot = 0.f;
        #pragma unroll 8
        for (int d4 = 0; d4 < 64; d4++) {
            float4 wv = __ldg(wr4 + d4);
            float4 zv = zr4[d4];
            dot = fmaf(zv.x, wv.x, dot);
            dot = fmaf(zv.y, wv.y, dot);
            dot = fmaf(zv.z, wv.z, dot);
            dot = fmaf(zv.w, wv.w, dot);
        }
        float v = __fsub_rn(__fadd_rn(zqv, g_wsq[k]), 2.0f * dot);
        unsigned long long key = ((unsigned long long)__float_as_uint(v) << 32) | (unsigned)k;
        if (key < best) best = key;
    }
    sbm[threadIdx.x] = best;
    __syncthreads();
    for (int s = 128; s > 0; s >>= 1) {
        if (threadIdx.x < s && sbm[threadIdx.x + s] < sbm[threadIdx.x])
            sbm[threadIdx.x] = sbm[threadIdx.x + s];
        __syncthreads();
    }
    if (threadIdx.x == 0) g_token[n] = (int)(sbm[0] & 0xffffffffull);
}

// ---------------- EMA / stats / output kernels ----------------
__global__ void k_scatter() {
    int n = blockIdx.x;
    int t = g_token[n];
    if (threadIdx.x == 0) atomicAdd(&g_counts[t], 1.0f);
    const float* src = g_zf + n * DDIM;
    float* dst = g_esum + t * DDIM;
    for (int d = threadIdx.x; d < DDIM; d += blockDim.x)
        atomicAdd(&dst[d], src[d]);
}

__global__ void k_cluster(const float* __restrict__ cs, float* __restrict__ ocn) {
    int k = blockIdx.x * 256 + threadIdx.x;
    float cnt = g_counts[k];
    float cn = 0.8f * cs[k] + 0.2f * cnt;
    ocn[k] = cn;
    float nz = (cnt > 0.f) ? 1.f : 0.f;
    float s_cn = cn, s_cnt = cnt, s_nz = nz;
    #pragma unroll
    for (int o = 16; o > 0; o >>= 1) {
        s_cn  += __shfl_down_sync(0xffffffffu, s_cn, o);
        s_cnt += __shfl_down_sync(0xffffffffu, s_cnt, o);
        s_nz  += __shfl_down_sync(0xffffffffu, s_nz, o);
    }
    if ((threadIdx.x & 31) == 0) {
        atomicAdd(&g_scal[1], s_cn);
        atomicAdd(&g_scal[2], s_cnt);
        atomicAdd(&g_scal[3], s_nz);
    }
}

__global__ void k_ema(const float* __restrict__ ea, float* __restrict__ oea) {
    int i = blockIdx.x * 256 + threadIdx.x;
    oea[i] = 0.8f * ea[i] + 0.2f * g_esum[i];
}

__global__ void k_entropy() {
    int k = blockIdx.x * 256 + threadIdx.x;
    float cnt = g_counts[k];
    float sumc = g_scal[2];
    float p = cnt / sumc;
    float term = p * logf(p + 1e-10f);
    #pragma unroll
    for (int o = 16; o > 0; o >>= 1) term += __shfl_down_sync(0xffffffffu, term, o);
    if ((threadIdx.x & 31) == 0) atomicAdd(&g_scal[4], term);
}

__global__ void k_weight(const float* __restrict__ ocn, const float* __restrict__ oea,
                         float* __restrict__ ow) {
    int i = blockIdx.x * 256 + threadIdx.x;
    int k = i >> 8;
    float cn = ocn[k];
    float n = g_scal[1];
    float t = (cn + 1e-5f) / (n + 0.16384f);
    float smv = t * n;
    ow[i] = oea[i] / smv;
}

__global__ void k_outloss(const float* __restrict__ z, const float* __restrict__ w,
                          float* __restrict__ oout) {
    int idx = blockIdx.x * 256 + threadIdx.x;
    int b = idx >> 18;
    int c = (idx >> 10) & 255;
    int p = idx & 1023;
    int n = (b << 10) | p;
    float zt = z[idx];
    float zqv = __ldg(&w[g_token[n] * DDIM + c]);
    float diff = __fsub_rn(zqv, zt);
    oout[idx] = __fadd_rn(zt, diff);
    float sq = diff * diff;
    sq = blockReduceSum(sq);
    if (threadIdx.x == 0) atomicAdd(&g_scal[0], sq);
}

__global__ void k_scalars(float* __restrict__ o) {
    float S = g_scal[0];
    o[0] = 0.25f * (S / 4194304.0f);
    o[1] = S / 16384.0f;
    o[2] = g_scal[3] / 16384.0f;
    o[3] = expf(-g_scal[4]);
}

// ---------------- launch ----------------
extern "C" void kernel_launch(void* const* d_in, const int* in_sizes, int n_in,
                              void* d_out, int out_size) {
    const float* z  = (const float*)d_in[0];
    const float* w  = (const float*)d_in[1];
    const float* cs = (const float*)d_in[2];
    const float* ea = (const float*)d_in[3];
    float* out = (float*)d_out;

    float* o_out  = out + O_OUT;
    float* o_scal = out + O_SCAL;
    float* o_wnew = out + O_WNEW;
    float* o_cnew = out + O_CNEW;
    float* o_ea   = out + O_EANEW;

    cudaFuncSetAttribute(k_screen, cudaFuncAttributeMaxDynamicSharedMemorySize, SCR_SMEM);

    k_zf2<<<dim3(32, 8, NBATCH), dim3(32, 8)>>>(z);   // launch 0
    k_zsq<<<N_TOK, 256>>>();                          // launch 1
    k_wsq2<<<KCB, 256>>>(w);                          // launch 2
    k_screen<<<N_TOK / 64, STHR, SCR_SMEM>>>();       // launch 3  (profiled slot)
    k_zero<<<(KCB * DDIM + 255) / 256, 256>>>();
    k_rescue<<<N_TOK / 8, 256>>>(w);
    k_rescue_ov<<<N_TOK, 256>>>(w);
    k_scatter<<<N_TOK, 128>>>();
    k_cluster<<<KCB / 256, 256>>>(cs, o_cnew);
    k_ema<<<(KCB * DDIM) / 256, 256>>>(ea, o_ea);
    k_entropy<<<KCB / 256, 256>>>();
    k_weight<<<(KCB * DDIM) / 256, 256>>>(o_cnew, o_ea, o_wnew);
    k_outloss<<<(NBATCH * DDIM * HWD) / 256, 256>>>(z, w, o_out);
    k_scalars<<<1, 1>>>(o_scal);
}

// round 15
// speedup vs baseline: 1.8161x; 1.1769x over previous
#include <cuda_runtime.h>
#include <cuda_bf16.h>
#include <math.h>

// ---------------- problem constants ----------------
#define N_TOK 16384
#define KCB   16384
#define DDIM  256
#define NBATCH 16
#define HWD   1024

#define O_OUT   0
#define O_SCAL  4194304
#define O_WNEW  4194308
#define O_CNEW  8388612
#define O_EANEW 8404996

#define CAPQ   16
#define NSUB   16
#define MARGIN 1e-3f

// ---------------- device scratch ----------------
__device__ float g_zf[N_TOK * DDIM];
__device__ float g_wsq[KCB];
__device__ float g_zsq[N_TOK];
__device__ int   g_token[N_TOK];
__device__ float g_counts[KCB];
__device__ float g_esum[KCB * DDIM];
__device__ float g_scal[8];
__device__ __nv_bfloat16 g_zbf[N_TOK * DDIM];
// B in screen layout: [64 chunks][4 quarters][256 rows x 128B, xor-swizzled]
__device__ unsigned char g_wbf[KCB * DDIM * 2];
__device__ int g_cand[N_TOK * NSUB * CAPQ];
__device__ int g_ccnt[N_TOK * NSUB];

// ---------------- helpers ----------------
__device__ __forceinline__ void cp_async16(void* smem_dst, const void* gsrc) {
    unsigned sa = (unsigned)__cvta_generic_to_shared(smem_dst);
    asm volatile("cp.async.cg.shared.global [%0], [%1], 16;" :: "r"(sa), "l"(gsrc));
}
#define CP_COMMIT() asm volatile("cp.async.commit_group;")

__device__ __forceinline__ void ldsm_x4(unsigned addr, unsigned& r0, unsigned& r1,
                                        unsigned& r2, unsigned& r3) {
    asm volatile("ldmatrix.sync.aligned.m8n8.x4.shared.b16 {%0,%1,%2,%3}, [%4];"
        : "=r"(r0), "=r"(r1), "=r"(r2), "=r"(r3) : "r"(addr));
}

__device__ __forceinline__ void mma16816(float* d, const unsigned* a, const unsigned* b) {
    asm volatile("mma.sync.aligned.m16n8k16.row.col.f32.bf16.bf16.f32 "
        "{%0,%1,%2,%3}, {%4,%5,%6,%7}, {%8,%9}, {%0,%1,%2,%3};"
        : "+f"(d[0]), "+f"(d[1]), "+f"(d[2]), "+f"(d[3])
        : "r"(a[0]), "r"(a[1]), "r"(a[2]), "r"(a[3]), "r"(b[0]), "r"(b[1]));
}

__device__ __forceinline__ void mbar_wait(unsigned addr, unsigned parity) {
    asm volatile(
        "{\n\t.reg .pred P;\n"
        "W%=:\n\t"
        "mbarrier.try_wait.parity.shared.b64 P, [%0], %1;\n\t"
        "@!P bra W%=;\n\t}"
        :: "r"(addr), "r"(parity) : "memory");
}

__device__ __forceinline__ float blockReduceSum(float v) {
    __shared__ float red[32];
    int lane = threadIdx.x & 31, wid = threadIdx.x >> 5;
    #pragma unroll
    for (int o = 16; o > 0; o >>= 1) v += __shfl_down_sync(0xffffffffu, v, o);
    if (lane == 0) red[wid] = v;
    __syncthreads();
    if (wid == 0) {
        v = (lane < ((blockDim.x + 31) >> 5)) ? red[lane] : 0.f;
        #pragma unroll
        for (int o = 16; o > 0; o >>= 1) v += __shfl_down_sync(0xffffffffu, v, o);
    }
    return v;
}

// ---------------- prep kernels ----------------
__global__ void k_zf2(const float* __restrict__ z) {
    __shared__ float t[32][33];
    int b = blockIdx.z;
    int c0 = blockIdx.x * 32;
    int r0 = blockIdx.y * 32;
    const float* src = z + b * DDIM * HWD;
    for (int i = threadIdx.y; i < 32; i += 8)
        t[i][threadIdx.x] = src[(r0 + i) * HWD + c0 + threadIdx.x];
    __syncthreads();
    float* dst = g_zf + b * HWD * DDIM;
    __nv_bfloat16* dstb = g_zbf + b * HWD * DDIM;
    for (int i = threadIdx.y; i < 32; i += 8) {
        float v = t[threadIdx.x][i];
        dst[(c0 + i) * DDIM + r0 + threadIdx.x] = v;
        dstb[(c0 + i) * DDIM + r0 + threadIdx.x] = __float2bfloat16(v);
    }
}

__global__ void k_zsq() {
    int r = blockIdx.x;
    float v = g_zf[r * DDIM + threadIdx.x];
    v *= v;
    v = blockReduceSum(v);
    if (threadIdx.x == 0) g_zsq[r] = v;
}

// wsq + bf16 conversion into the swizzled screen layout
__global__ void k_wsq2(const float* __restrict__ w) {
    int r = blockIdx.x;
    int d = threadIdx.x;
    float v0 = w[r * DDIM + d];
    // chunk = r>>8 (256 codes), quarter = d>>6 (64 dims = 128B)
    int off = ((r & 255) * 128) + ((d & 63) * 2);
    int swz = off ^ ((off >> 3) & 0x70);
    *(__nv_bfloat16*)(g_wbf + (size_t)(r >> 8) * 131072 + (size_t)(d >> 6) * 32768 + swz) =
        __float2bfloat16(v0);
    float v = v0 * v0;
    v = blockReduceSum(v);
    if (d == 0) g_wsq[r] = v;
}

__global__ void k_zero() {
    int i = blockIdx.x * blockDim.x + threadIdx.x;
    if (i < KCB * DDIM) g_esum[i] = 0.f;
    if (i < KCB) g_counts[i] = 0.f;
    if (i < 8) g_scal[i] = 0.f;
}

// ---------------- bf16 mma.sync screen ----------------
// 2 CTAs/SM. CTA: 64 tokens; chunk = 256 codes, B staged as k-QUARTER tiles
// (256 rows x 128B, xor-swizzled, loaded with ONE cp.async.bulk each),
// double-buffered via mbarrier. 8 warps (2m x 4n), warp tile 32x64.
#define SROW 528                   // A row pitch (256 bf16 + 16B pad)
#define A_BYTES (64 * SROW)        // 33792
#define B_BYTES 32768
#define B0_OFF  A_BYTES
#define B1_OFF  (A_BYTES + B_BYTES)
#define RMIN_OFF (A_BYTES + 2 * B_BYTES)     // 99328
#define MBAR_OFF (RMIN_OFF + 256)            // 99584
#define SCR_SMEM (MBAR_OFF + 32)             // 99616
#define STHR 256

// A tile: 64 rows x 512B
__device__ __forceinline__ void load_tile_A(char* dst, const char* gsrc, int tid) {
    #pragma unroll
    for (int it = 0; it < 8; it++) {
        int j = tid + it * STHR;
        int r = j >> 5, e = j & 31;
        cp_async16(dst + r * SROW + e * 16, gsrc + (size_t)r * 512 + e * 16);
    }
}

__global__ void __launch_bounds__(STHR, 2) k_screen() {
    extern __shared__ char sm[];
    unsigned sb = (unsigned)__cvta_generic_to_shared(sm);
    unsigned* s_rmin = (unsigned*)(sm + RMIN_OFF);
    unsigned sbm = sb + MBAR_OFF;
    int tid = threadIdx.x, lane = tid & 31, wid = tid >> 5;
    int wm = wid >> 2, wn = wid & 3;      // 2m x 4n; warp tile 32 x 64
    int gm0 = blockIdx.x * 64;
    int quad = lane & 3;

    if (tid < 64) s_rmin[tid] = 0x7f800000u;
    if (tid == 0) {
        asm volatile("mbarrier.init.shared.b64 [%0], 1;" :: "r"(sbm) : "memory");
        asm volatile("mbarrier.init.shared.b64 [%0], 1;" :: "r"(sbm + 8) : "memory");
    }
    load_tile_A(sm, (const char*)g_zbf + (size_t)gm0 * 512, tid);
    CP_COMMIT();
    __syncthreads();          // mbar init + rmin visible

    if (tid == 0) {
        asm volatile("mbarrier.arrive.expect_tx.shared.b64 _, [%0], %1;"
                     :: "r"(sbm), "r"((unsigned)B_BYTES) : "memory");
        asm volatile("cp.async.bulk.shared::cta.global.mbarrier::complete_tx::bytes "
                     "[%0], [%1], %2, [%3];"
                     :: "r"(sb + B0_OFF), "l"((const char*)g_wbf), "r"((unsigned)B_BYTES),
                        "r"(sbm) : "memory");
    }
    asm volatile("cp.async.wait_group 0;");   // own A parts done
    __syncthreads();                          // everyone's A parts done

    int trow[4]; float zq[4]; float rmin[4]; int cnt[4];
    #pragma unroll
    for (int mt = 0; mt < 2; mt++)
        #pragma unroll
        for (int h = 0; h < 2; h++) {
            int s = mt * 2 + h;
            trow[s] = wm * 32 + mt * 16 + h * 8 + (lane >> 2);
            zq[s] = g_zsq[gm0 + trow[s]];
            rmin[s] = __int_as_float(0x7f800000);
            cnt[s] = 0;
        }

    unsigned a_off = (unsigned)((wm * 32 + (lane & 15)) * SROW + ((lane >> 4) * 8) * 2);
    // B per-lane swizzled base: row0*128 + seg0*16, xor-swizzled
    int brow0 = wn * 64 + ((lane >> 4) & 1) * 8 + (lane & 7);
    int bbase = brow0 * 128 + ((lane >> 3) & 1) * 16;
    unsigned b_swz = (unsigned)(bbase ^ ((bbase >> 3) & 0x70));

    float acc[2][8][4];   // 64 regs

    #pragma unroll 1
    for (int hh = 0; hh < 256; hh++) {       // 64 chunks x 4 k-quarters
        int cb = hh >> 2, q = hh & 3;
        if (tid == 0 && hh + 1 < 256) {
            unsigned mb = sbm + (((hh + 1) & 1) << 3);
            const char* gsrc = (const char*)g_wbf
                + (size_t)((hh + 1) >> 2) * 131072 + (size_t)((hh + 1) & 3) * 32768;
            unsigned dst = sb + (((hh + 1) & 1) ? B1_OFF : B0_OFF);
            asm volatile("mbarrier.arrive.expect_tx.shared.b64 _, [%0], %1;"
                         :: "r"(mb), "r"((unsigned)B_BYTES) : "memory");
            asm volatile("cp.async.bulk.shared::cta.global.mbarrier::complete_tx::bytes "
                         "[%0], [%1], %2, [%3];"
                         :: "r"(dst), "l"(gsrc), "r"((unsigned)B_BYTES), "r"(mb) : "memory");
        }
        mbar_wait(sbm + ((hh & 1) << 3), (hh >> 1) & 1);

        if (q == 0) {
            #pragma unroll
            for (int mt = 0; mt < 2; mt++)
                #pragma unroll
                for (int nt = 0; nt < 8; nt++)
                    #pragma unroll
                    for (int r = 0; r < 4; r++) acc[mt][nt][r] = 0.f;
        }

        unsigned bb = sb + ((hh & 1) ? B1_OFF : B0_OFF);
        #pragma unroll
        for (int kk = 0; kk < 4; kk++) {     // 4 k-chunks of 16 within quarter
            int kc = q * 4 + kk;             // global k-chunk for A
            unsigned a[2][4], b[8][2];
            #pragma unroll
            for (int mt = 0; mt < 2; mt++)
                ldsm_x4(sb + a_off + mt * 16 * SROW + kc * 32,
                        a[mt][0], a[mt][1], a[mt][2], a[mt][3]);
            #pragma unroll
            for (int hf = 0; hf < 4; hf++) {
                unsigned r0, r1, r2, r3;
                ldsm_x4((bb + b_swz + hf * 2048) ^ (unsigned)(kk << 5), r0, r1, r2, r3);
                b[hf * 2][0] = r0; b[hf * 2][1] = r1;
                b[hf * 2 + 1][0] = r2; b[hf * 2 + 1][1] = r3;
            }
            #pragma unroll
            for (int mt = 0; mt < 2; mt++)
                #pragma unroll
                for (int nt = 0; nt < 8; nt++)
                    mma16816(acc[mt][nt], a[mt], b[nt]);
        }

        if (q == 3) {
            // epilogue over 256 codes (R11 structure)
            int npass = (cb == 0) ? 2 : 1;
            for (int pass = 0; pass < npass; pass++) {
                bool capture = (pass == npass - 1);
                if (cb == 0 && pass == 1) __syncthreads();
                float cur[4];
                #pragma unroll
                for (int s = 0; s < 4; s++)
                    cur[s] = fminf(rmin[s], __uint_as_float(s_rmin[trow[s]]));
                #pragma unroll
                for (int nt = 0; nt < 8; nt++) {
                    int kg = cb * 256 + wn * 64 + nt * 8 + quad * 2;
                    float w0 = __ldg(g_wsq + kg), w1 = __ldg(g_wsq + kg + 1);
                    #pragma unroll
                    for (int mt = 0; mt < 2; mt++)
                        #pragma unroll
                        for (int h = 0; h < 2; h++) {
                            int s = mt * 2 + h;
                            float v0 = fmaf(-2.f, acc[mt][nt][h * 2 + 0], zq[s] + w0);
                            float v1 = fmaf(-2.f, acc[mt][nt][h * 2 + 1], zq[s] + w1);
                            if (capture) {
                                int tokg = gm0 + trow[s];
                                if (v0 <= cur[s] + MARGIN) {
                                    if (cnt[s] < CAPQ)
                                        g_cand[((tokg * 4 + wn) * 4 + quad) * CAPQ + cnt[s]] = kg;
                                    cnt[s]++;
                                }
                                if (v1 <= cur[s] + MARGIN) {
                                    if (cnt[s] < CAPQ)
                                        g_cand[((tokg * 4 + wn) * 4 + quad) * CAPQ + cnt[s]] = kg + 1;
                                    cnt[s]++;
                                }
                            }
                            cur[s] = fminf(cur[s], fminf(v0, v1));
                        }
                }
                #pragma unroll
                for (int s = 0; s < 4; s++) {
                    rmin[s] = cur[s];
                    atomicMin(&s_rmin[trow[s]], __float_as_uint(cur[s]));
                }
            }
        }
        __syncthreads();
    }
    #pragma unroll
    for (int s = 0; s < 4; s++)
        g_ccnt[((gm0 + trow[s]) * 4 + wn) * 4 + quad] = cnt[s];
}

// ---------------- exact fp32 rescue (warp per token, coalesced dots) ----------------
__global__ void __launch_bounds__(256) k_rescue(const float* __restrict__ w) {
    __shared__ int s_list[8][NSUB * CAPQ];
    int warp = threadIdx.x >> 5, lane = threadIdx.x & 31;
    int n = blockIdx.x * 8 + warp;

    int myc = (lane < NSUB) ? g_ccnt[n * NSUB + lane] : 0;
    unsigned ovmask = __ballot_sync(0xffffffffu, myc > CAPQ);
    if (ovmask) return;   // handled by k_rescue_ov (rare)

    int p = myc;
    #pragma unroll
    for (int o = 1; o < 32; o <<= 1) {
        int t = __shfl_up_sync(0xffffffffu, p, o);
        if (lane >= o) p += t;
    }
    int base = p - myc;
    int total = __shfl_sync(0xffffffffu, p, 31);
    const int* lst = g_cand + (n * NSUB + lane) * CAPQ;
    for (int i = 0; i < myc; i++) s_list[warp][base + i] = lst[i];
    __syncwarp();

    const float4* zr4 = (const float4*)(g_zf + (size_t)n * DDIM);
    float4 zv0 = zr4[lane], zv1 = zr4[lane + 32];
    float zqv = g_zsq[n];
    unsigned long long best = ~0ull;

    for (int ci = 0; ci < total; ci++) {
        int k = s_list[warp][ci];
        const float4* wr4 = (const float4*)(w + (size_t)k * DDIM);
        float4 wv0 = __ldg(wr4 + lane), wv1 = __ldg(wr4 + lane + 32);
        float dot = 0.f;
        dot = fmaf(zv0.x, wv0.x, dot); dot = fmaf(zv0.y, wv0.y, dot);
        dot = fmaf(zv0.z, wv0.z, dot); dot = fmaf(zv0.w, wv0.w, dot);
        dot = fmaf(zv1.x, wv1.x, dot); dot = fmaf(zv1.y, wv1.y, dot);
        dot = fmaf(zv1.z, wv1.z, dot); dot = fmaf(zv1.w, wv1.w, dot);
        #pragma unroll
        for (int o = 16; o > 0; o >>= 1) dot += __shfl_xor_sync(0xffffffffu, dot, o);
        float v = __fsub_rn(__fadd_rn(zqv, g_wsq[k]), 2.0f * dot);
        unsigned long long key = ((unsigned long long)__float_as_uint(v) << 32) | (unsigned)k;
        if (key < best) best = key;
    }
    if (lane == 0) g_token[n] = (int)(best & 0xffffffffull);
}

// deterministic full scan for (rare) overflow tokens — cheap early-out
__global__ void k_rescue_ov(const float* __restrict__ w) {
    int n = blockIdx.x;
    __shared__ int ovf;
    if (threadIdx.x == 0) ovf = 0;
    __syncthreads();
    if (threadIdx.x < NSUB && g_ccnt[n * NSUB + threadIdx.x] > CAPQ) ovf = 1;
    __syncthreads();
    if (!ovf) return;

    __shared__ unsigned long long sbm[256];
    const float4* zr4 = (const float4*)(g_zf + (size_t)n * DDIM);
    float zqv = g_zsq[n];
    unsigned long long best = ~0ull;
    for (int k = threadIdx.x; k < KCB; k += 256) {
        const float4* wr4 = (const float4*)(w + (size_t)k * DDIM);
        float dot = 0.f;
        #pragma unroll 8
        for (int d4 = 0; d4 < 64; d4++) {
            float4 wv = __ldg(wr4 + d4);
            float4 zv = zr4[d4];
            dot = fmaf(zv.x, wv.x, dot);
            dot = fmaf(zv.y, wv.y, dot);
            dot = fmaf(zv.z, wv.z, dot);
            dot = fmaf(zv.w, wv.w, dot);
        }
        float v = __fsub_rn(__fadd_rn(zqv, g_wsq[k]), 2.0f * dot);
        unsigned long long key = ((unsigned long long)__float_as_uint(v) << 32) | (unsigned)k;
        if (key < best) best = key;
    }
    sbm[threadIdx.x] = best;
    __syncthreads();
    for (int s = 128; s > 0; s >>= 1) {
        if (threadIdx.x < s && sbm[threadIdx.x + s] < sbm[threadIdx.x])
            sbm[threadIdx.x] = sbm[threadIdx.x + s];
        __syncthreads();
    }
    if (threadIdx.x == 0) g_token[n] = (int)(sbm[0] & 0xffffffffull);
}

// ---------------- EMA / stats / output kernels ----------------
__global__ void k_scatter() {
    int n = blockIdx.x;
    int t = g_token[n];
    if (threadIdx.x == 0) atomicAdd(&g_counts[t], 1.0f);
    const float* src = g_zf + n * DDIM;
    float* dst = g_esum + t * DDIM;
    for (int d = threadIdx.x; d < DDIM; d += blockDim.x)
        atomicAdd(&dst[d], src[d]);
}

__global__ void k_cluster(const float* __restrict__ cs, float* __restrict__ ocn) {
    int k = blockIdx.x * 256 + threadIdx.x;
    float cnt = g_counts[k];
    float cn = 0.8f * cs[k] + 0.2f * cnt;
    ocn[k] = cn;
    float nz = (cnt > 0.f) ? 1.f : 0.f;
    float s_cn = cn, s_cnt = cnt, s_nz = nz;
    #pragma unroll
    for (int o = 16; o > 0; o >>= 1) {
        s_cn  += __shfl_down_sync(0xffffffffu, s_cn, o);
        s_cnt += __shfl_down_sync(0xffffffffu, s_cnt, o);
        s_nz  += __shfl_down_sync(0xffffffffu, s_nz, o);
    }
    if ((threadIdx.x & 31) == 0) {
        atomicAdd(&g_scal[1], s_cn);
        atomicAdd(&g_scal[2], s_cnt);
        atomicAdd(&g_scal[3], s_nz);
    }
}

__global__ void k_ema(const float* __restrict__ ea, float* __restrict__ oea) {
    int i = blockIdx.x * 256 + threadIdx.x;
    oea[i] = 0.8f * ea[i] + 0.2f * g_esum[i];
}

__global__ void k_entropy() {
    int k = blockIdx.x * 256 + threadIdx.x;
    float cnt = g_counts[k];
    float sumc = g_scal[2];
    float p = cnt / sumc;
    float term = p * logf(p + 1e-10f);
    #pragma unroll
    for (int o = 16; o > 0; o >>= 1) term += __shfl_down_sync(0xffffffffu, term, o);
    if ((threadIdx.x & 31) == 0) atomicAdd(&g_scal[4], term);
}

__global__ void k_weight(const float* __restrict__ ocn, const float* __restrict__ oea,
                         float* __restrict__ ow) {
    int i = blockIdx.x * 256 + threadIdx.x;
    int k = i >> 8;
    float cn = ocn[k];
    float n = g_scal[1];
    float t = (cn + 1e-5f) / (n + 0.16384f);
    float smv = t * n;
    ow[i] = oea[i] / smv;
}

__global__ void k_outloss(const float* __restrict__ z, const float* __restrict__ w,
                          float* __restrict__ oout) {
    int idx = blockIdx.x * 256 + threadIdx.x;
    int b = idx >> 18;
    int c = (idx >> 10) & 255;
    int p = idx & 1023;
    int n = (b << 10) | p;
    float zt = z[idx];
    float zqv = __ldg(&w[g_token[n] * DDIM + c]);
    float diff = __fsub_rn(zqv, zt);
    oout[idx] = __fadd_rn(zt, diff);
    float sq = diff * diff;
    sq = blockReduceSum(sq);
    if (threadIdx.x == 0) atomicAdd(&g_scal[0], sq);
}

__global__ void k_scalars(float* __restrict__ o) {
    float S = g_scal[0];
    o[0] = 0.25f * (S / 4194304.0f);
    o[1] = S / 16384.0f;
    o[2] = g_scal[3] / 16384.0f;
    o[3] = expf(-g_scal[4]);
}

// ---------------- launch ----------------
extern "C" void kernel_launch(void* const* d_in, const int* in_sizes, int n_in,
                              void* d_out, int out_size) {
    const float* z  = (const float*)d_in[0];
    const float* w  = (const float*)d_in[1];
    const float* cs = (const float*)d_in[2];
    const float* ea = (const float*)d_in[3];
    float* out = (float*)d_out;

    float* o_out  = out + O_OUT;
    float* o_scal = out + O_SCAL;
    float* o_wnew = out + O_WNEW;
    float* o_cnew = out + O_CNEW;
    float* o_ea   = out + O_EANEW;

    cudaFuncSetAttribute(k_screen, cudaFuncAttributeMaxDynamicSharedMemorySize, SCR_SMEM);

    k_zf2<<<dim3(32, 8, NBATCH), dim3(32, 8)>>>(z);   // launch 0
    k_zsq<<<N_TOK, 256>>>();                          // launch 1
    k_wsq2<<<KCB, 256>>>(w);                          // launch 2
    k_screen<<<N_TOK / 64, STHR, SCR_SMEM>>>();       // launch 3  (profiled slot)
    k_zero<<<(KCB * DDIM + 255) / 256, 256>>>();
    k_rescue<<<N_TOK / 8, 256>>>(w);
    k_rescue_ov<<<N_TOK, 256>>>(w);
    k_scatter<<<N_TOK, 128>>>();
    k_cluster<<<KCB / 256, 256>>>(cs, o_cnew);
    k_ema<<<(KCB * DDIM) / 256, 256>>>(ea, o_ea);
    k_entropy<<<KCB / 256, 256>>>();
    k_weight<<<(KCB * DDIM) / 256, 256>>>(o_cnew, o_ea, o_wnew);
    k_outloss<<<(NBATCH * DDIM * HWD) / 256, 256>>>(z, w, o_out);
    k_scalars<<<1, 1>>>(o_scal);
}

// round 16
// speedup vs baseline: 1.9569x; 1.0775x over previous
#include <cuda_runtime.h>
#include <cuda_bf16.h>
#include <math.h>

// ---------------- problem constants ----------------
#define N_TOK 16384
#define KCB   16384
#define DDIM  256
#define NBATCH 16
#define HWD   1024

#define O_OUT   0
#define O_SCAL  4194304
#define O_WNEW  4194308
#define O_CNEW  8388612
#define O_EANEW 8404996

#define CAPQ   16
#define NSUB   16
#define MARGIN 1e-3f

// ---------------- device scratch ----------------
__device__ float g_zf[N_TOK * DDIM];
__device__ float g_wsq[KCB];
__device__ float g_zsq[N_TOK];
__device__ int   g_token[N_TOK];
__device__ float g_counts[KCB];
__device__ float g_esum[KCB * DDIM];
__device__ float g_scal[8];
__device__ __nv_bfloat16 g_zbf[N_TOK * DDIM];
// B in screen layout: [64 chunks][4 quarters][256 rows x 128B, xor-swizzled]
__device__ unsigned char g_wbf[KCB * DDIM * 2];
__device__ int g_cand[N_TOK * NSUB * CAPQ];
__device__ int g_ccnt[N_TOK * NSUB];

// ---------------- helpers ----------------
__device__ __forceinline__ void cp_async16(void* smem_dst, const void* gsrc) {
    unsigned sa = (unsigned)__cvta_generic_to_shared(smem_dst);
    asm volatile("cp.async.cg.shared.global [%0], [%1], 16;" :: "r"(sa), "l"(gsrc));
}
#define CP_COMMIT() asm volatile("cp.async.commit_group;")

__device__ __forceinline__ void ldsm_x4(unsigned addr, unsigned& r0, unsigned& r1,
                                        unsigned& r2, unsigned& r3) {
    asm volatile("ldmatrix.sync.aligned.m8n8.x4.shared.b16 {%0,%1,%2,%3}, [%4];"
        : "=r"(r0), "=r"(r1), "=r"(r2), "=r"(r3) : "r"(addr));
}

__device__ __forceinline__ void mma16816(float* d, const unsigned* a, const unsigned* b) {
    asm volatile("mma.sync.aligned.m16n8k16.row.col.f32.bf16.bf16.f32 "
        "{%0,%1,%2,%3}, {%4,%5,%6,%7}, {%8,%9}, {%0,%1,%2,%3};"
        : "+f"(d[0]), "+f"(d[1]), "+f"(d[2]), "+f"(d[3])
        : "r"(a[0]), "r"(a[1]), "r"(a[2]), "r"(a[3]), "r"(b[0]), "r"(b[1]));
}

__device__ __forceinline__ void mbar_wait(unsigned addr, unsigned parity) {
    asm volatile(
        "{\n\t.reg .pred P;\n"
        "W%=:\n\t"
        "mbarrier.try_wait.parity.shared.b64 P, [%0], %1;\n\t"
        "@!P bra W%=;\n\t}"
        :: "r"(addr), "r"(parity) : "memory");
}

__device__ __forceinline__ void mbar_arrive(unsigned addr) {
    asm volatile("mbarrier.arrive.shared.b64 _, [%0];" :: "r"(addr) : "memory");
}

__device__ __forceinline__ float blockReduceSum(float v) {
    __shared__ float red[32];
    int lane = threadIdx.x & 31, wid = threadIdx.x >> 5;
    #pragma unroll
    for (int o = 16; o > 0; o >>= 1) v += __shfl_down_sync(0xffffffffu, v, o);
    if (lane == 0) red[wid] = v;
    __syncthreads();
    if (wid == 0) {
        v = (lane < ((blockDim.x + 31) >> 5)) ? red[lane] : 0.f;
        #pragma unroll
        for (int o = 16; o > 0; o >>= 1) v += __shfl_down_sync(0xffffffffu, v, o);
    }
    return v;
}

// ---------------- prep kernels ----------------
__global__ void k_zf2(const float* __restrict__ z) {
    __shared__ float t[32][33];
    int b = blockIdx.z;
    int c0 = blockIdx.x * 32;
    int r0 = blockIdx.y * 32;
    const float* src = z + b * DDIM * HWD;
    for (int i = threadIdx.y; i < 32; i += 8)
        t[i][threadIdx.x] = src[(r0 + i) * HWD + c0 + threadIdx.x];
    __syncthreads();
    float* dst = g_zf + b * HWD * DDIM;
    __nv_bfloat16* dstb = g_zbf + b * HWD * DDIM;
    for (int i = threadIdx.y; i < 32; i += 8) {
        float v = t[threadIdx.x][i];
        dst[(c0 + i) * DDIM + r0 + threadIdx.x] = v;
        dstb[(c0 + i) * DDIM + r0 + threadIdx.x] = __float2bfloat16(v);
    }
}

__global__ void k_zsq() {
    int r = blockIdx.x;
    float v = g_zf[r * DDIM + threadIdx.x];
    v *= v;
    v = blockReduceSum(v);
    if (threadIdx.x == 0) g_zsq[r] = v;
}

// wsq + bf16 conversion into the swizzled screen layout
__global__ void k_wsq2(const float* __restrict__ w) {
    int r = blockIdx.x;
    int d = threadIdx.x;
    float v0 = w[r * DDIM + d];
    int off = ((r & 255) * 128) + ((d & 63) * 2);
    int swz = off ^ ((off >> 3) & 0x70);
    *(__nv_bfloat16*)(g_wbf + (size_t)(r >> 8) * 131072 + (size_t)(d >> 6) * 32768 + swz) =
        __float2bfloat16(v0);
    float v = v0 * v0;
    v = blockReduceSum(v);
    if (d == 0) g_wsq[r] = v;
}

__global__ void k_zero() {
    int i = blockIdx.x * blockDim.x + threadIdx.x;
    if (i < KCB * DDIM) g_esum[i] = 0.f;
    if (i < KCB) g_counts[i] = 0.f;
    if (i < 8) g_scal[i] = 0.f;
}

// ---------------- bf16 mma.sync screen ----------------
// 2 CTAs/SM, 8 warps, warp tile 32x64, chunk = 256 codes, B staged as k-quarter
// tiles (32KB) via cp.async.bulk, double-buffered with a full/empty mbarrier
// ring. NO block-wide barrier in the main loop: warps free-run so one warp's
// HMMA overlaps another's LDSM (R15 showed they serialize under __syncthreads).
#define SROW 528                   // A row pitch (256 bf16 + 16B pad)
#define A_BYTES (64 * SROW)        // 33792
#define B_BYTES 32768
#define B0_OFF  A_BYTES
#define B1_OFF  (A_BYTES + B_BYTES)
#define RMIN_OFF (A_BYTES + 2 * B_BYTES)     // 99328
#define MBAR_OFF (RMIN_OFF + 256)            // 99584: full0 full1 empty0 empty1
#define SCR_SMEM (MBAR_OFF + 64)
#define STHR 256

// A tile: 64 rows x 512B
__device__ __forceinline__ void load_tile_A(char* dst, const char* gsrc, int tid) {
    #pragma unroll
    for (int it = 0; it < 8; it++) {
        int j = tid + it * STHR;
        int r = j >> 5, e = j & 31;
        cp_async16(dst + r * SROW + e * 16, gsrc + (size_t)r * 512 + e * 16);
    }
}

__global__ void __launch_bounds__(STHR, 2) k_screen() {
    extern __shared__ char sm[];
    unsigned sb = (unsigned)__cvta_generic_to_shared(sm);
    unsigned* s_rmin = (unsigned*)(sm + RMIN_OFF);
    unsigned mb_full = sb + MBAR_OFF;          // +0, +8
    unsigned mb_empty = sb + MBAR_OFF + 16;    // +16, +24
    int tid = threadIdx.x, lane = tid & 31, wid = tid >> 5;
    int wm = wid >> 2, wn = wid & 3;      // 2m x 4n; warp tile 32 x 64
    int gm0 = blockIdx.x * 64;
    int quad = lane & 3;

    if (tid < 64) s_rmin[tid] = 0x7f800000u;
    if (tid == 0) {
        asm volatile("mbarrier.init.shared.b64 [%0], 1;" :: "r"(mb_full) : "memory");
        asm volatile("mbarrier.init.shared.b64 [%0], 1;" :: "r"(mb_full + 8) : "memory");
        asm volatile("mbarrier.init.shared.b64 [%0], 8;" :: "r"(mb_empty) : "memory");
        asm volatile("mbarrier.init.shared.b64 [%0], 8;" :: "r"(mb_empty + 8) : "memory");
    }
    load_tile_A(sm, (const char*)g_zbf + (size_t)gm0 * 512, tid);
    CP_COMMIT();
    __syncthreads();          // mbar init + rmin visible

    if (tid == 0) {
        asm volatile("mbarrier.arrive.expect_tx.shared.b64 _, [%0], %1;"
                     :: "r"(mb_full), "r"((unsigned)B_BYTES) : "memory");
        asm volatile("cp.async.bulk.shared::cta.global.mbarrier::complete_tx::bytes "
                     "[%0], [%1], %2, [%3];"
                     :: "r"(sb + B0_OFF), "l"((const char*)g_wbf), "r"((unsigned)B_BYTES),
                        "r"(mb_full) : "memory");
    }
    asm volatile("cp.async.wait_group 0;");   // own A parts done
    __syncthreads();                          // everyone's A parts done

    int trow[4]; float zq[4]; float rmin[4]; int cnt[4];
    #pragma unroll
    for (int mt = 0; mt < 2; mt++)
        #pragma unroll
        for (int h = 0; h < 2; h++) {
            int s = mt * 2 + h;
            trow[s] = wm * 32 + mt * 16 + h * 8 + (lane >> 2);
            zq[s] = g_zsq[gm0 + trow[s]];
            rmin[s] = __int_as_float(0x7f800000);
            cnt[s] = 0;
        }

    unsigned a_off = (unsigned)((wm * 32 + (lane & 15)) * SROW + ((lane >> 4) * 8) * 2);
    int brow0 = wn * 64 + ((lane >> 4) & 1) * 8 + (lane & 7);
    int bbase = brow0 * 128 + ((lane >> 3) & 1) * 16;
    unsigned b_swz = (unsigned)(bbase ^ ((bbase >> 3) & 0x70));

    float acc[2][8][4];   // 64 regs

    #pragma unroll 1
    for (int hh = 0; hh < 256; hh++) {       // 64 chunks x 4 k-quarters
        int cb = hh >> 2, q = hh & 3;
        if (tid == 0 && hh + 1 < 256) {
            int nf = hh + 1;
            unsigned mb = mb_full + ((nf & 1) << 3);
            if (nf >= 2) {
                // wait for all 8 warps done with this buffer's previous use
                mbar_wait(mb_empty + ((nf & 1) << 3), (((nf >> 1) + 1) & 1));
            }
            const char* gsrc = (const char*)g_wbf
                + (size_t)(nf >> 2) * 131072 + (size_t)(nf & 3) * 32768;
            unsigned dst = sb + ((nf & 1) ? B1_OFF : B0_OFF);
            asm volatile("mbarrier.arrive.expect_tx.shared.b64 _, [%0], %1;"
                         :: "r"(mb), "r"((unsigned)B_BYTES) : "memory");
            asm volatile("cp.async.bulk.shared::cta.global.mbarrier::complete_tx::bytes "
                         "[%0], [%1], %2, [%3];"
                         :: "r"(dst), "l"(gsrc), "r"((unsigned)B_BYTES), "r"(mb) : "memory");
        }
        mbar_wait(mb_full + ((hh & 1) << 3), (hh >> 1) & 1);

        if (q == 0) {
            #pragma unroll
            for (int mt = 0; mt < 2; mt++)
                #pragma unroll
                for (int nt = 0; nt < 8; nt++)
                    #pragma unroll
                    for (int r = 0; r < 4; r++) acc[mt][nt][r] = 0.f;
        }

        unsigned bb = sb + ((hh & 1) ? B1_OFF : B0_OFF);
        #pragma unroll
        for (int kk = 0; kk < 4; kk++) {     // 4 k-chunks of 16 within quarter
            int kc = q * 4 + kk;             // global k-chunk for A
            unsigned a[2][4], b[8][2];
            #pragma unroll
            for (int mt = 0; mt < 2; mt++)
                ldsm_x4(sb + a_off + mt * 16 * SROW + kc * 32,
                        a[mt][0], a[mt][1], a[mt][2], a[mt][3]);
            #pragma unroll
            for (int hf = 0; hf < 4; hf++) {
                unsigned r0, r1, r2, r3;
                ldsm_x4((bb + b_swz + hf * 2048) ^ (unsigned)(kk << 5), r0, r1, r2, r3);
                b[hf * 2][0] = r0; b[hf * 2][1] = r1;
                b[hf * 2 + 1][0] = r2; b[hf * 2 + 1][1] = r3;
            }
            #pragma unroll
            for (int mt = 0; mt < 2; mt++)
                #pragma unroll
                for (int nt = 0; nt < 8; nt++)
                    mma16816(acc[mt][nt], a[mt], b[nt]);
        }
        // done reading this buffer: signal producer (lane 0 per warp, count=8)
        if (lane == 0) mbar_arrive(mb_empty + ((hh & 1) << 3));

        if (q == 3) {
            // epilogue over 256 codes; capture vs block-shared (racy-but-monotone)
            // running min — any subset-min upper-bounds the global approx min,
            // so capture-set completeness holds under free-running warps.
            int npass = (cb == 0) ? 2 : 1;
            for (int pass = 0; pass < npass; pass++) {
                bool capture = (pass == npass - 1);
                float cur[4];
                #pragma unroll
                for (int s = 0; s < 4; s++)
                    cur[s] = fminf(rmin[s], __uint_as_float(s_rmin[trow[s]]));
                #pragma unroll
                for (int nt = 0; nt < 8; nt++) {
                    int kg = cb * 256 + wn * 64 + nt * 8 + quad * 2;
                    float w0 = __ldg(g_wsq + kg), w1 = __ldg(g_wsq + kg + 1);
                    #pragma unroll
                    for (int mt = 0; mt < 2; mt++)
                        #pragma unroll
                        for (int h = 0; h < 2; h++) {
                            int s = mt * 2 + h;
                            float v0 = fmaf(-2.f, acc[mt][nt][h * 2 + 0], zq[s] + w0);
                            float v1 = fmaf(-2.f, acc[mt][nt][h * 2 + 1], zq[s] + w1);
                            if (capture) {
                                int tokg = gm0 + trow[s];
                                if (v0 <= cur[s] + MARGIN) {
                                    if (cnt[s] < CAPQ)
                                        g_cand[((tokg * 4 + wn) * 4 + quad) * CAPQ + cnt[s]] = kg;
                                    cnt[s]++;
                                }
                                if (v1 <= cur[s] + MARGIN) {
                                    if (cnt[s] < CAPQ)
                                        g_cand[((tokg * 4 + wn) * 4 + quad) * CAPQ + cnt[s]] = kg + 1;
                                    cnt[s]++;
                                }
                            }
                            cur[s] = fminf(cur[s], fminf(v0, v1));
                        }
                }
                #pragma unroll
                for (int s = 0; s < 4; s++) {
                    rmin[s] = cur[s];
                    atomicMin(&s_rmin[trow[s]], __float_as_uint(cur[s]));
                }
            }
        }
    }
    #pragma unroll
    for (int s = 0; s < 4; s++)
        g_ccnt[((gm0 + trow[s]) * 4 + wn) * 4 + quad] = cnt[s];
}

// ---------------- exact fp32 rescue (warp per token, coalesced dots) ----------------
__global__ void __launch_bounds__(256) k_rescue(const float* __restrict__ w) {
    __shared__ int s_list[8][NSUB * CAPQ];
    int warp = threadIdx.x >> 5, lane = threadIdx.x & 31;
    int n = blockIdx.x * 8 + warp;

    int myc = (lane < NSUB) ? g_ccnt[n * NSUB + lane] : 0;
    unsigned ovmask = __ballot_sync(0xffffffffu, myc > CAPQ);
    if (ovmask) return;   // handled by k_rescue_ov (rare)

    int p = myc;
    #pragma unroll
    for (int o = 1; o < 32; o <<= 1) {
        int t = __shfl_up_sync(0xffffffffu, p, o);
        if (lane >= o) p += t;
    }
    int base = p - myc;
    int total = __shfl_sync(0xffffffffu, p, 31);
    const int* lst = g_cand + (n * NSUB + lane) * CAPQ;
    for (int i = 0; i < myc; i++) s_list[warp][base + i] = lst[i];
    __syncwarp();

    const float4* zr4 = (const float4*)(g_zf + (size_t)n * DDIM);
    float4 zv0 = zr4[lane], zv1 = zr4[lane + 32];
    float zqv = g_zsq[n];
    unsigned long long best = ~0ull;

    for (int ci = 0; ci < total; ci++) {
        int k = s_list[warp][ci];
        const float4* wr4 = (const float4*)(w + (size_t)k * DDIM);
        float4 wv0 = __ldg(wr4 + lane), wv1 = __ldg(wr4 + lane + 32);
        float dot = 0.f;
        dot = fmaf(zv0.x, wv0.x, dot); dot = fmaf(zv0.y, wv0.y, dot);
        dot = fmaf(zv0.z, wv0.z, dot); dot = fmaf(zv0.w, wv0.w, dot);
        dot = fmaf(zv1.x, wv1.x, dot); dot = fmaf(zv1.y, wv1.y, dot);
        dot = fmaf(zv1.z, wv1.z, dot); dot = fmaf(zv1.w, wv1.w, dot);
        #pragma unroll
        for (int o = 16; o > 0; o >>= 1) dot += __shfl_xor_sync(0xffffffffu, dot, o);
        float v = __fsub_rn(__fadd_rn(zqv, g_wsq[k]), 2.0f * dot);
        unsigned long long key = ((unsigned long long)__float_as_uint(v) << 32) | (unsigned)k;
        if (key < best) best = key;
    }
    if (lane == 0) g_token[n] = (int)(best & 0xffffffffull);
}

// deterministic full scan for (rare) overflow tokens — cheap early-out
__global__ void k_rescue_ov(const float* __restrict__ w) {
    int n = blockIdx.x;
    __shared__ int ovf;
    if (threadIdx.x == 0) ovf = 0;
    __syncthreads();
    if (threadIdx.x < NSUB && g_ccnt[n * NSUB + threadIdx.x] > CAPQ) ovf = 1;
    __syncthreads();
    if (!ovf) return;

    __shared__ unsigned long long sbm[256];
    const float4* zr4 = (const float4*)(g_zf + (size_t)n * DDIM);
    float zqv = g_zsq[n];
    unsigned long long best = ~0ull;
    for (int k = threadIdx.x; k < KCB; k += 256) {
        const float4* wr4 = (const float4*)(w + (size_t)k * DDIM);
        float dot = 0.f;
        #pragma unroll 8
        for (int d4 = 0; d4 < 64; d4++) {
            float4 wv = __ldg(wr4 + d4);
            float4 zv = zr4[d4];
            dot = fmaf(zv.x, wv.x, dot);
            dot = fmaf(zv.y, wv.y, dot);
            dot = fmaf(zv.z, wv.z, dot);
            dot = fmaf(zv.w, wv.w, dot);
        }
        float v = __fsub_rn(__fadd_rn(zqv, g_wsq[k]), 2.0f * dot);
        unsigned long long key = ((unsigned long long)__float_as_uint(v) << 32) | (unsigned)k;
        if (key < best) best = key;
    }
    sbm[threadIdx.x] = best;
    __syncthreads();
    for (int s = 128; s > 0; s >>= 1) {
        if (threadIdx.x < s && sbm[threadIdx.x + s] < sbm[threadIdx.x])
            sbm[threadIdx.x] = sbm[threadIdx.x + s];
        __syncthreads();
    }
    if (threadIdx.x == 0) g_token[n] = (int)(sbm[0] & 0xffffffffull);
}

// ---------------- EMA / stats / output kernels ----------------
__global__ void k_scatter() {
    int n = blockIdx.x;
    int t = g_token[n];
    if (threadIdx.x == 0) atomicAdd(&g_counts[t], 1.0f);
    const float* src = g_zf + n * DDIM;
    float* dst = g_esum + t * DDIM;
    for (int d = threadIdx.x; d < DDIM; d += blockDim.x)
        atomicAdd(&dst[d], src[d]);
}

// cluster EMA + utilization + entropy (sum(counts) == 16384.0 exactly in fp32)
__global__ void k_cluster(const float* __restrict__ cs, float* __restrict__ ocn) {
    int k = blockIdx.x * 256 + threadIdx.x;
    float cnt = g_counts[k];
    float cn = 0.8f * cs[k] + 0.2f * cnt;
    ocn[k] = cn;
    float nz = (cnt > 0.f) ? 1.f : 0.f;
    float pp = cnt / 16384.0f;
    float term = pp * logf(pp + 1e-10f);
    float s_cn = cn, s_nz = nz, s_t = term;
    #pragma unroll
    for (int o = 16; o > 0; o >>= 1) {
        s_cn += __shfl_down_sync(0xffffffffu, s_cn, o);
        s_nz += __shfl_down_sync(0xffffffffu, s_nz, o);
        s_t  += __shfl_down_sync(0xffffffffu, s_t, o);
    }
    if ((threadIdx.x & 31) == 0) {
        atomicAdd(&g_scal[1], s_cn);
        atomicAdd(&g_scal[3], s_nz);
        atomicAdd(&g_scal[4], s_t);
    }
}

__global__ void k_ema(const float* __restrict__ ea, float* __restrict__ oea) {
    int i = blockIdx.x * 256 + threadIdx.x;
    oea[i] = 0.8f * ea[i] + 0.2f * g_esum[i];
}

__global__ void k_weight(const float* __restrict__ ocn, const float* __restrict__ oea,
                         float* __restrict__ ow) {
    int i = blockIdx.x * 256 + threadIdx.x;
    int k = i >> 8;
    float cn = ocn[k];
    float n = g_scal[1];
    float t = (cn + 1e-5f) / (n + 0.16384f);
    float smv = t * n;
    ow[i] = oea[i] / smv;
}

__global__ void k_outloss(const float* __restrict__ z, const float* __restrict__ w,
                          float* __restrict__ oout) {
    int idx = blockIdx.x * 256 + threadIdx.x;
    int b = idx >> 18;
    int c = (idx >> 10) & 255;
    int p = idx & 1023;
    int n = (b << 10) | p;
    float zt = z[idx];
    float zqv = __ldg(&w[g_token[n] * DDIM + c]);
    float diff = __fsub_rn(zqv, zt);
    oout[idx] = __fadd_rn(zt, diff);
    float sq = diff * diff;
    sq = blockReduceSum(sq);
    if (threadIdx.x == 0) atomicAdd(&g_scal[0], sq);
}

__global__ void k_scalars(float* __restrict__ o) {
    float S = g_scal[0];
    o[0] = 0.25f * (S / 4194304.0f);
    o[1] = S / 16384.0f;
    o[2] = g_scal[3] / 16384.0f;
    o[3] = expf(-g_scal[4]);
}

// ---------------- launch ----------------
extern "C" void kernel_launch(void* const* d_in, const int* in_sizes, int n_in,
                              void* d_out, int out_size) {
    const float* z  = (const float*)d_in[0];
    const float* w  = (const float*)d_in[1];
    const float* cs = (const float*)d_in[2];
    const float* ea = (const float*)d_in[3];
    float* out = (float*)d_out;

    float* o_out  = out + O_OUT;
    float* o_scal = out + O_SCAL;
    float* o_wnew = out + O_WNEW;
    float* o_cnew = out + O_CNEW;
    float* o_ea   = out + O_EANEW;

    cudaFuncSetAttribute(k_screen, cudaFuncAttributeMaxDynamicSharedMemorySize, SCR_SMEM);

    k_zf2<<<dim3(32, 8, NBATCH), dim3(32, 8)>>>(z);   // launch 0
    k_zsq<<<N_TOK, 256>>>();                          // launch 1
    k_wsq2<<<KCB, 256>>>(w);                          // launch 2
    k_screen<<<N_TOK / 64, STHR, SCR_SMEM>>>();       // launch 3  (profiled slot)
    k_zero<<<(KCB * DDIM + 255) / 256, 256>>>();
    k_rescue<<<N_TOK / 8, 256>>>(w);
    k_rescue_ov<<<N_TOK, 256>>>(w);
    k_scatter<<<N_TOK, 128>>>();
    k_cluster<<<KCB / 256, 256>>>(cs, o_cnew);
    k_ema<<<(KCB * DDIM) / 256, 256>>>(ea, o_ea);
    k_weight<<<(KCB * DDIM) / 256, 256>>>(o_cnew, o_ea, o_wnew);
    k_outloss<<<(NBATCH * DDIM * HWD) / 256, 256>>>(z, w, o_out);
    k_scalars<<<1, 1>>>(o_scal);
}